// round 2
// baseline (speedup 1.0000x reference)
#include <cuda_runtime.h>
#include <cstdint>
#include <cstddef>

#define HWC 9216
#define EPSN 1e-5f

// ---------------- scratch (__device__ globals; no allocation) ----------------
__device__ float g_y1[75497472];      // conv1 output [128,64,9216]
__device__ float g_logits[1179648];   // [128,9216]
__device__ float g_cof[1179648];      // [128,9216]
__device__ float g_g2[1179648];       // gen-block intermediate [8,16,9216]
__device__ float g_tsum[512];         // sum_hw sr [8,64]
__device__ float g_T1[512];           // sum_hw tg
__device__ float g_T2[512];           // sum_hw tg^2
__device__ float g_op[8192];          // [128,64]
__device__ float g_u[8192];           // W^T opn
__device__ float g_v[8192];           // sum_hw sr*cof
__device__ float g_A1[8192];          // GN affine scale (reused GN1 then GN2)
__device__ float g_D1[8192];          // GN affine shift
__device__ float g_gn2s[8192];        // per-channel sums for GN2
__device__ float g_gn2q[8192];
__device__ float g_mstat[256];        // per-bn (mu, invstd) of msk for IN1
__device__ float g_in2s[128];
__device__ float g_in2q[128];
__device__ float g_in2stat[256];
__device__ float g_lossp[128];

// ---------------- helpers ----------------
__device__ __forceinline__ float wred(float v) {
#pragma unroll
    for (int o = 16; o > 0; o >>= 1) v += __shfl_xor_sync(0xffffffffu, v, o);
    return v;
}
__device__ __forceinline__ float bsum256(float v, float* red) {
    int t = threadIdx.x; red[t] = v; __syncthreads();
#pragma unroll
    for (int s = 128; s > 0; s >>= 1) { if (t < s) red[t] += red[t + s]; __syncthreads(); }
    float r = red[0]; __syncthreads(); return r;
}
__device__ __forceinline__ float bmax256(float v, float* red) {
    int t = threadIdx.x; red[t] = v; __syncthreads();
#pragma unroll
    for (int s = 128; s > 0; s >>= 1) { if (t < s) red[t] = fmaxf(red[t], red[t + s]); __syncthreads(); }
    float r = red[0]; __syncthreads(); return r;
}

// ---------------- 1: per-(b,c) sums of sr / tg / tg^2 ----------------
__global__ void k_colsum(const float* __restrict__ sr, const float* __restrict__ tg) {
    int bc = blockIdx.x;
    const float* ps = sr + (size_t)bc * HWC;
    const float* pt = tg + (size_t)bc * HWC;
    float s0 = 0.f, s1 = 0.f, s2 = 0.f;
    for (int i = threadIdx.x; i < HWC; i += 256) {
        s0 += ps[i];
        float t = pt[i]; s1 += t; s2 += t * t;
    }
    __shared__ float red[256];
    s0 = bsum256(s0, red); s1 = bsum256(s1, red); s2 = bsum256(s2, red);
    if (threadIdx.x == 0) { g_tsum[bc] = s0; g_T1[bc] = s1; g_T2[bc] = s2; }
}

// ---------------- 2: op0 = W * colsum(sr) + w_b * HW ----------------
__global__ void k_op0(const float* __restrict__ ww, const float* __restrict__ wb) {
    int bn = blockIdx.x; int b = bn >> 4, n = bn & 15; int cp = threadIdx.x;
    __shared__ float ts[64];
    ts[cp] = g_tsum[b * 64 + cp];
    __syncthreads();
    const float* wr = ww + (size_t)(n * 64 + cp) * 64;
    float a = 0.f;
#pragma unroll 8
    for (int c = 0; c < 64; c++) a = fmaf(wr[c], ts[c], a);
    g_op[bn * 64 + cp] = a + wb[n * 64 + cp] * (float)HWC;
}

// ---------------- 3a: opn, u = W^T opn; zero g_v ----------------
__global__ void k_u(const float* __restrict__ ww) {
    int bn = blockIdx.x; int n = bn & 15; int c = threadIdx.x;
    __shared__ float opn[64]; __shared__ float red[64];
    float o = g_op[bn * 64 + c];
    red[c] = o * o; __syncthreads();
#pragma unroll
    for (int s = 32; s > 0; s >>= 1) { if (c < s) red[c] += red[c + s]; __syncthreads(); }
    float nrm = fmaxf(sqrtf(red[0]), 1e-12f);
    opn[c] = o / nrm;
    __syncthreads();
    float u = 0.f;
    for (int cp = 0; cp < 64; cp++) u = fmaf(ww[(size_t)(n * 64 + cp) * 64 + c], opn[cp], u);
    g_u[bn * 64 + c] = u;
    g_v[bn * 64 + c] = 0.f;
}

// ---------------- 3b: logits[b,n,hw] = sum_c u[b,n,c]*sr[b,c,hw] ----------------
__global__ void k_logits(const float* __restrict__ sr) {
    int b = blockIdx.y;
    int hw = blockIdx.x * 256 + threadIdx.x;
    __shared__ float us[1024];
    for (int i = threadIdx.x; i < 1024; i += 256) us[i] = g_u[b * 1024 + i];
    __syncthreads();
    float acc[16];
#pragma unroll
    for (int n = 0; n < 16; n++) acc[n] = 0.f;
    const float* sp = sr + (size_t)b * 64 * HWC + hw;
    for (int c = 0; c < 64; c++) {
        float v = sp[(size_t)c * HWC];
#pragma unroll
        for (int n = 0; n < 16; n++) acc[n] = fmaf(us[n * 64 + c], v, acc[n]);
    }
#pragma unroll
    for (int n = 0; n < 16; n++) g_logits[(size_t)(b * 16 + n) * HWC + hw] = acc[n];
}

// ---------------- 3c: softmax over hw (optionally also to d_out cof) ----------------
__global__ void k_softmax(float* extra) {
    int bn = blockIdx.x;
    const float* l = g_logits + (size_t)bn * HWC;
    __shared__ float red[256];
    float mx = -1e30f;
    for (int i = threadIdx.x; i < HWC; i += 256) mx = fmaxf(mx, l[i]);
    mx = bmax256(mx, red);
    float se = 0.f;
    for (int i = threadIdx.x; i < HWC; i += 256) se += expf(l[i] - mx);
    se = bsum256(se, red);
    float inv = 1.f / se;
    float* cf = g_cof + (size_t)bn * HWC;
    float* ex = extra ? extra + (size_t)bn * HWC : nullptr;
    for (int i = threadIdx.x; i < HWC; i += 256) {
        float c = expf(l[i] - mx) * inv;
        cf[i] = c;
        if (ex) ex[i] = c;
    }
}

// ---------------- 3d: v[b,n,c] = sum_hw sr[b,c,hw]*cof[b,n,hw] ----------------
__global__ void k_v(const float* __restrict__ sr) {
    int ch = blockIdx.x;   // 16 chunks of 576 pixels
    int b  = blockIdx.y;
    int hw0 = ch * 576;
    __shared__ float cof_s[16 * 576];
    for (int idx = threadIdx.x; idx < 9216; idx += 256) {
        int n = idx / 576, k = idx - n * 576;
        cof_s[n * 576 + k] = g_cof[(size_t)(b * 16 + n) * HWC + hw0 + k];
    }
    __syncthreads();
    int w = threadIdx.x >> 5, lane = threadIdx.x & 31;
    for (int c = w; c < 64; c += 8) {
        const float* sp = sr + (size_t)(b * 64 + c) * HWC + hw0;
        float a[16];
#pragma unroll
        for (int n = 0; n < 16; n++) a[n] = 0.f;
        for (int k = lane; k < 576; k += 32) {
            float s = sp[k];
#pragma unroll
            for (int n = 0; n < 16; n++) a[n] = fmaf(s, cof_s[n * 576 + k], a[n]);
        }
#pragma unroll
        for (int n = 0; n < 16; n++) {
            float r = wred(a[n]);
            if (lane == 0) atomicAdd(&g_v[(b * 16 + n) * 64 + c], r);
        }
    }
}

// ---------------- 3e: op = W v + w_b ----------------
__global__ void k_op(const float* __restrict__ ww, const float* __restrict__ wb) {
    int bn = blockIdx.x; int n = bn & 15; int cp = threadIdx.x;
    __shared__ float vs[64];
    vs[cp] = g_v[bn * 64 + cp];
    __syncthreads();
    const float* wr = ww + (size_t)(n * 64 + cp) * 64;
    float a = 0.f;
#pragma unroll 8
    for (int c = 0; c < 64; c++) a = fmaf(wr[c], vs[c], a);
    g_op[bn * 64 + cp] = a + wb[n * 64 + cp];
}

// ---------------- 4: analytic GN1 affine; zero GN2 accumulators ----------------
__global__ void k_gn1AD(const float* __restrict__ g1g, const float* __restrict__ g1b) {
    int bn = blockIdx.x; int b = bn >> 4; int c = threadIdx.x;
    float op = g_op[bn * 64 + c];
    float t1 = g_T1[b * 64 + c], t2 = g_T2[b * 64 + c];
    float s1 = t1 + 9216.f * op;
    float s2 = t2 + 2.f * op * t1 + 9216.f * op * op;
    s1 += __shfl_xor_sync(0xffffffffu, s1, 1); s1 += __shfl_xor_sync(0xffffffffu, s1, 2);
    s2 += __shfl_xor_sync(0xffffffffu, s2, 1); s2 += __shfl_xor_sync(0xffffffffu, s2, 2);
    float mu  = s1 * (1.f / 36864.f);
    float var = s2 * (1.f / 36864.f) - mu * mu;
    float inv = rsqrtf(var + EPSN);
    g_A1[bn * 64 + c] = g1g[c] * inv;
    g_D1[bn * 64 + c] = (op - mu) * inv * g1g[c] + g1b[c];
    g_gn2s[bn * 64 + c] = 0.f; g_gn2q[bn * 64 + c] = 0.f;
}

// ---------------- 5: fused GN1+ReLU+conv3x3(64->64)+GN2-stat epilogue ----------------
__global__ void __launch_bounds__(256, 2) k_conv1(const float* __restrict__ tg,
                                                  const float* __restrict__ c1w,
                                                  const float* __restrict__ c1b) {
    int bn = blockIdx.z, b = bn >> 4;
    int gx0 = blockIdx.x * 8, gy0 = blockIdx.y * 16;
    int tid = threadIdx.x, wid = tid >> 5, lane = tid & 31;
    int r0 = (lane >> 2) * 2, c0 = (lane & 3) * 2;
    __shared__ float in_s[1440];            // 8 cin x 18 x 10 (halo tile)
    __shared__ float w_s[4608];             // [cin][tap][co]
    __shared__ float As[64], Ds[64], Bs[64];
    if (tid < 64) { As[tid] = g_A1[bn * 64 + tid]; Ds[tid] = g_D1[bn * 64 + tid]; Bs[tid] = c1b[tid]; }
    float acc[8][4];
#pragma unroll
    for (int i = 0; i < 8; i++) { acc[i][0] = 0.f; acc[i][1] = 0.f; acc[i][2] = 0.f; acc[i][3] = 0.f; }
    const float* tgb = tg + (size_t)b * 64 * HWC;

    for (int cc = 0; cc < 64; cc += 8) {
        __syncthreads();
        for (int idx = tid; idx < 1440; idx += 256) {
            int cin = idx / 180, rem = idx - cin * 180, r = rem / 10, c = rem - r * 10;
            int gy = gy0 + r - 1, gx = gx0 + c - 1;
            float v = 0.f;
            if (gy >= 0 && gy < 96 && gx >= 0 && gx < 96) {
                float t = tgb[(size_t)(cc + cin) * HWC + gy * 96 + gx];
                v = fmaxf(fmaf(t, As[cc + cin], Ds[cc + cin]), 0.f);
            }
            in_s[idx] = v;
        }
        for (int idx = tid; idx < 4608; idx += 256) {
            int co = idx & 63, rest = idx >> 6, cin = rest / 9, tap = rest - cin * 9;
            w_s[(cin * 9 + tap) * 64 + co] = c1w[(size_t)(co * 64 + cc + cin) * 9 + tap];
        }
        __syncthreads();
#pragma unroll
        for (int cin = 0; cin < 8; cin++) {
            float win[4][4];
#pragma unroll
            for (int i = 0; i < 4; i++)
#pragma unroll
                for (int j = 0; j < 4; j++)
                    win[i][j] = in_s[cin * 180 + (r0 + i) * 10 + (c0 + j)];
#pragma unroll
            for (int kr = 0; kr < 3; kr++)
#pragma unroll
                for (int kc = 0; kc < 3; kc++) {
                    int wb = (cin * 9 + kr * 3 + kc) * 64 + wid * 8;
#pragma unroll
                    for (int co = 0; co < 8; co++) {
                        float wv = w_s[wb + co];
                        acc[co][0] = fmaf(wv, win[kr][kc],         acc[co][0]);
                        acc[co][1] = fmaf(wv, win[kr][kc + 1],     acc[co][1]);
                        acc[co][2] = fmaf(wv, win[kr + 1][kc],     acc[co][2]);
                        acc[co][3] = fmaf(wv, win[kr + 1][kc + 1], acc[co][3]);
                    }
                }
        }
    }
#pragma unroll
    for (int co = 0; co < 8; co++) {
        int cog = wid * 8 + co;
        float bsv = Bs[cog];
        float s = 0.f, q = 0.f;
#pragma unroll
        for (int p = 0; p < 4; p++) {
            float v = acc[co][p] + bsv;
            int rr = r0 + (p >> 1), ccol = c0 + (p & 1);
            g_y1[(size_t)(bn * 64 + cog) * HWC + (gy0 + rr) * 96 + gx0 + ccol] = v;
            s += v; q += v * v;
        }
        s = wred(s); q = wred(q);
        if (lane == 0) { atomicAdd(&g_gn2s[bn * 64 + cog], s); atomicAdd(&g_gn2q[bn * 64 + cog], q); }
    }
}

// ---------------- 6: GN2 affine params (reuse g_A1/g_D1) ----------------
__global__ void k_gn2fin(const float* __restrict__ g2g, const float* __restrict__ g2b) {
    int bn = blockIdx.x, c = threadIdx.x;
    float s = g_gn2s[bn * 64 + c], q = g_gn2q[bn * 64 + c];
    s += __shfl_xor_sync(0xffffffffu, s, 1); s += __shfl_xor_sync(0xffffffffu, s, 2);
    q += __shfl_xor_sync(0xffffffffu, q, 1); q += __shfl_xor_sync(0xffffffffu, q, 2);
    float mu = s * (1.f / 36864.f), var = q * (1.f / 36864.f) - mu * mu;
    float inv = rsqrtf(var + EPSN);
    g_A1[bn * 64 + c] = g2g[c] * inv;
    g_D1[bn * 64 + c] = g2b[c] - mu * inv * g2g[c];
}

// ---------------- 7: fused GN2+ReLU+conv3x3(64->1) -> msk ----------------
__global__ void __launch_bounds__(256) k_conv2(const float* __restrict__ c2w,
                                               const float* __restrict__ c2b,
                                               float* __restrict__ msk) {
    int bn = blockIdx.z; int gy0 = blockIdx.y * 16, gx0 = blockIdx.x * 16;
    int t = threadIdx.x, ty = t >> 4, tx = t & 15;
    __shared__ float tile[324];   // 18x18
    __shared__ float w2[576];
    __shared__ float A[64], D[64];
    for (int i = t; i < 576; i += 256) w2[i] = c2w[i];
    if (t < 64) { A[t] = g_A1[bn * 64 + t]; D[t] = g_D1[bn * 64 + t]; }
    float acc = c2b[0];
    const float* y = g_y1 + (size_t)bn * 64 * HWC;
    for (int ch = 0; ch < 64; ch++) {
        __syncthreads();
        for (int idx = t; idx < 324; idx += 256) {
            int r = idx / 18, c = idx - r * 18;
            int gy = gy0 + r - 1, gx = gx0 + c - 1;
            float v = 0.f;
            if (gy >= 0 && gy < 96 && gx >= 0 && gx < 96)
                v = fmaxf(fmaf(y[(size_t)ch * HWC + gy * 96 + gx], A[ch], D[ch]), 0.f);
            tile[idx] = v;
        }
        __syncthreads();
#pragma unroll
        for (int kr = 0; kr < 3; kr++)
#pragma unroll
            for (int kc = 0; kc < 3; kc++)
                acc = fmaf(w2[ch * 9 + kr * 3 + kc], tile[(ty + kr) * 18 + tx + kc], acc);
    }
    msk[(size_t)bn * HWC + (gy0 + ty) * 96 + gx0 + tx] = acc;
}

// ---------------- 8: per-bn softmax of msk, center loss, IN1 stats ----------------
__global__ void k_msk_stats(const float* __restrict__ msk) {
    int bn = blockIdx.x; int t = threadIdx.x;
    const float* m = msk + (size_t)bn * HWC;
    __shared__ float red[256];
    float mx = -1e30f;
    for (int i = t; i < HWC; i += 256) mx = fmaxf(mx, m[i]);
    mx = bmax256(mx, red);
    float se = 0.f, s1 = 0.f, s2 = 0.f;
    for (int i = t; i < HWC; i += 256) { float v = m[i]; se += expf(v - mx); s1 += v; s2 += v * v; }
    se = bsum256(se, red); s1 = bsum256(s1, red); s2 = bsum256(s2, red);
    float inv_se = 1.f / se;
    float ey = 0.f, ex = 0.f, ey2 = 0.f, ex2 = 0.f;
    const float st = 2.f / 95.f;
    for (int i = t; i < HWC; i += 256) {
        float c = expf(m[i] - mx) * inv_se;
        int ii = i / 96, jj = i - ii * 96;
        float yv = -1.f + st * ii, xv = -1.f + st * jj;
        ey += c * yv; ex += c * xv; ey2 += c * yv * yv; ex2 += c * xv * xv;
    }
    ey = bsum256(ey, red); ex = bsum256(ex, red);
    ey2 = bsum256(ey2, red); ex2 = bsum256(ex2, red);
    if (t == 0) {
        g_lossp[bn] = ey2 - ey * ey + ex2 - ex * ex;
        float mu = s1 / 9216.f; float var = s2 / 9216.f - mu * mu;
        g_mstat[2 * bn] = mu; g_mstat[2 * bn + 1] = rsqrtf(var + EPSN);
        g_in2s[bn] = 0.f; g_in2q[bn] = 0.f;
    }
}

// ---------------- 9: centr loss reduction ----------------
__global__ void k_loss(float* out) {
    __shared__ float red[128];
    int t = threadIdx.x;
    red[t] = g_lossp[t]; __syncthreads();
#pragma unroll
    for (int s = 64; s > 0; s >>= 1) { if (t < s) red[t] += red[t + s]; __syncthreads(); }
    if (t == 0) out[0] = red[0] * (1.f / 128.f);
}

// ---------------- 10: IN1+ReLU+1x1 conv (16->16) + IN2 stat accumulation ----------------
__global__ void k_gen1(const float* __restrict__ msk, const float* __restrict__ in1g,
                       const float* __restrict__ in1b, const float* __restrict__ c3w,
                       const float* __restrict__ c3b) {
    int b = blockIdx.y; int hw = blockIdx.x * 256 + threadIdx.x;
    int t = threadIdx.x;
    __shared__ float w3[256], b3[16], mus[16], invs[16], g1[16], bb1[16];
    __shared__ float bs_[16], bq_[16];
    if (t < 256) w3[t] = c3w[t];
    if (t < 16) {
        b3[t] = c3b[t]; int bn = b * 16 + t;
        mus[t] = g_mstat[2 * bn]; invs[t] = g_mstat[2 * bn + 1];
        g1[t] = in1g[t]; bb1[t] = in1b[t]; bs_[t] = 0.f; bq_[t] = 0.f;
    }
    __syncthreads();
    float r[16];
#pragma unroll
    for (int n = 0; n < 16; n++) {
        float m = msk[(size_t)(b * 16 + n) * HWC + hw];
        r[n] = fmaxf((m - mus[n]) * invs[n] * g1[n] + bb1[n], 0.f);
    }
#pragma unroll
    for (int o = 0; o < 16; o++) {
        float a = b3[o];
#pragma unroll
        for (int n = 0; n < 16; n++) a = fmaf(w3[o * 16 + n], r[n], a);
        g_g2[(size_t)(b * 16 + o) * HWC + hw] = a;
        float s = wred(a), q = wred(a * a);
        if ((t & 31) == 0) { atomicAdd(&bs_[o], s); atomicAdd(&bq_[o], q); }
    }
    __syncthreads();
    if (t < 16) { atomicAdd(&g_in2s[b * 16 + t], bs_[t]); atomicAdd(&g_in2q[b * 16 + t], bq_[t]); }
}

// ---------------- 11: IN2 stats finalize ----------------
__global__ void k_in2fin() {
    int i = threadIdx.x;
    float mu = g_in2s[i] / 9216.f;
    float var = g_in2q[i] / 9216.f - mu * mu;
    g_in2stat[2 * i] = mu; g_in2stat[2 * i + 1] = rsqrtf(var + EPSN);
}

// ---------------- 12: IN2+ReLU+1x1(16->3)+sigmoid -> rec ----------------
__global__ void k_rec(const float* __restrict__ in2g, const float* __restrict__ in2b,
                      const float* __restrict__ c4w, const float* __restrict__ c4b,
                      float* __restrict__ out) {
    int b = blockIdx.y; int hw = blockIdx.x * 256 + threadIdx.x; int t = threadIdx.x;
    __shared__ float w4[48], mus[16], invs[16], g2[16], bb2[16];
    if (t < 48) w4[t] = c4w[t];
    if (t < 16) {
        int bo = b * 16 + t;
        mus[t] = g_in2stat[2 * bo]; invs[t] = g_in2stat[2 * bo + 1];
        g2[t] = in2g[t]; bb2[t] = in2b[t];
    }
    __syncthreads();
    float x[16];
#pragma unroll
    for (int o = 0; o < 16; o++) {
        float v = g_g2[(size_t)(b * 16 + o) * HWC + hw];
        x[o] = fmaxf((v - mus[o]) * invs[o] * g2[o] + bb2[o], 0.f);
    }
#pragma unroll
    for (int o2 = 0; o2 < 3; o2++) {
        float a = c4b[o2];
#pragma unroll
        for (int o = 0; o < 16; o++) a = fmaf(w4[o2 * 16 + o], x[o], a);
        out[(size_t)(b * 3 + o2) * HWC + hw] = 1.f / (1.f + expf(-a));
    }
}

// ---------------- 13: op_out = op[bnc] * msk[bn,hw] ----------------
__global__ void k_opout(const float* __restrict__ msk, float* __restrict__ out) {
    int bn = blockIdx.y; int hw = blockIdx.x * 256 + threadIdx.x;
    __shared__ float ops[64];
    if (threadIdx.x < 64) ops[threadIdx.x] = g_op[bn * 64 + threadIdx.x];
    __syncthreads();
    float m = msk[(size_t)bn * HWC + hw];
    float* o = out + (size_t)bn * 64 * HWC + hw;
#pragma unroll 8
    for (int c = 0; c < 64; c++) o[(size_t)c * HWC] = ops[c] * m;
}

// ---------------- launch ----------------
extern "C" void kernel_launch(void* const* d_in, const int* in_sizes, int n_in,
                              void* d_out, int out_size) {
    const float* sr   = (const float*)d_in[0];
    const float* tg   = (const float*)d_in[1];
    const float* ww   = (const float*)d_in[2];
    const float* wb   = (const float*)d_in[3];
    const float* gn1g = (const float*)d_in[4];
    const float* gn1b = (const float*)d_in[5];
    const float* c1w  = (const float*)d_in[6];
    const float* c1b  = (const float*)d_in[7];
    const float* gn2g = (const float*)d_in[8];
    const float* gn2b = (const float*)d_in[9];
    const float* c2w  = (const float*)d_in[10];
    const float* c2b  = (const float*)d_in[11];
    const float* in1g = (const float*)d_in[12];
    const float* in1b = (const float*)d_in[13];
    const float* c3w  = (const float*)d_in[14];
    const float* c3b  = (const float*)d_in[15];
    const float* c4w  = (const float*)d_in[18];
    const float* c4b  = (const float*)d_in[19];
    const float* in2g = (const float*)d_in[16];
    const float* in2b = (const float*)d_in[17];
    float* out = (float*)d_out;
    float* out_msk  = out + 75497472;
    float* out_rec  = out + 76677120;
    float* out_loss = out + 76898304;
    float* out_cof  = out + 76898305;

    k_colsum<<<512, 256>>>(sr, tg);
    k_op0<<<128, 64>>>(ww, wb);
    for (int it = 0; it < 3; it++) {
        k_u<<<128, 64>>>(ww);
        k_logits<<<dim3(36, 8), 256>>>(sr);
        k_softmax<<<128, 256>>>(it == 2 ? out_cof : (float*)nullptr);
        k_v<<<dim3(16, 8), 256>>>(sr);
        k_op<<<128, 64>>>(ww, wb);
    }
    k_gn1AD<<<128, 64>>>(gn1g, gn1b);
    k_conv1<<<dim3(12, 6, 128), 256>>>(tg, c1w, c1b);
    k_gn2fin<<<128, 64>>>(gn2g, gn2b);
    k_conv2<<<dim3(6, 6, 128), 256>>>(c2w, c2b, out_msk);
    k_msk_stats<<<128, 256>>>(out_msk);
    k_loss<<<1, 128>>>(out_loss);
    k_gen1<<<dim3(36, 8), 256>>>(out_msk, in1g, in1b, c3w, c3b);
    k_in2fin<<<1, 128>>>();
    k_rec<<<dim3(36, 8), 256>>>(in2g, in2b, c4w, c4b, out_rec);
    k_opout<<<dim3(36, 128), 256>>>(out_msk, out);
}

// round 3
// speedup vs baseline: 1.8215x; 1.8215x over previous
#include <cuda_runtime.h>
#include <cstdint>
#include <cstddef>

#define HWC 9216
#define EPSN 1e-5f

// ---------------- scratch (__device__ globals; no allocation) ----------------
__device__ float g_y1[75497472];      // conv1 output [128,64,9216]
__device__ float g_logits[1179648];   // [128,9216]
__device__ float g_cof[1179648];      // [128,9216]
__device__ float g_g2[1179648];       // gen-block intermediate [8,16,9216]
__device__ float g_tsum[512];         // sum_hw sr [8,64]
__device__ float g_T1[512];           // sum_hw tg
__device__ float g_T2[512];           // sum_hw tg^2
__device__ float g_op[8192];          // [128,64]
__device__ float g_u[8192];           // W^T opn
__device__ float g_v[8192];           // sum_hw sr*cof
__device__ float g_A1[8192];          // GN affine scale (reused GN1 then GN2)
__device__ float g_D1[8192];          // GN affine shift
__device__ float g_gn2s[8192];        // per-channel sums for GN2
__device__ float g_gn2q[8192];
__device__ float g_mstat[256];        // per-bn (mu, invstd) of msk for IN1
__device__ float g_in2s[128];
__device__ float g_in2q[128];
__device__ float g_in2stat[256];
__device__ float g_lossp[128];

// ---------------- helpers ----------------
__device__ __forceinline__ float wred(float v) {
#pragma unroll
    for (int o = 16; o > 0; o >>= 1) v += __shfl_xor_sync(0xffffffffu, v, o);
    return v;
}
__device__ __forceinline__ float bsum256(float v, float* red) {
    int t = threadIdx.x; red[t] = v; __syncthreads();
#pragma unroll
    for (int s = 128; s > 0; s >>= 1) { if (t < s) red[t] += red[t + s]; __syncthreads(); }
    float r = red[0]; __syncthreads(); return r;
}
__device__ __forceinline__ float bmax256(float v, float* red) {
    int t = threadIdx.x; red[t] = v; __syncthreads();
#pragma unroll
    for (int s = 128; s > 0; s >>= 1) { if (t < s) red[t] = fmaxf(red[t], red[t + s]); __syncthreads(); }
    float r = red[0]; __syncthreads(); return r;
}
__device__ __forceinline__ uint32_t f2tf32(float v) {
    uint32_t r;
    asm("cvt.rna.tf32.f32 %0, %1;" : "=r"(r) : "f"(v));
    return r;
}

// ---------------- 1: per-(b,c) sums of sr / tg / tg^2 ----------------
__global__ void k_colsum(const float* __restrict__ sr, const float* __restrict__ tg) {
    int bc = blockIdx.x;
    const float* ps = sr + (size_t)bc * HWC;
    const float* pt = tg + (size_t)bc * HWC;
    float s0 = 0.f, s1 = 0.f, s2 = 0.f;
    for (int i = threadIdx.x; i < HWC; i += 256) {
        s0 += ps[i];
        float t = pt[i]; s1 += t; s2 += t * t;
    }
    __shared__ float red[256];
    s0 = bsum256(s0, red); s1 = bsum256(s1, red); s2 = bsum256(s2, red);
    if (threadIdx.x == 0) { g_tsum[bc] = s0; g_T1[bc] = s1; g_T2[bc] = s2; }
}

// ---------------- 2: op0 = W * colsum(sr) + w_b * HW ----------------
__global__ void k_op0(const float* __restrict__ ww, const float* __restrict__ wb) {
    int bn = blockIdx.x; int b = bn >> 4, n = bn & 15; int cp = threadIdx.x;
    __shared__ float ts[64];
    ts[cp] = g_tsum[b * 64 + cp];
    __syncthreads();
    const float* wr = ww + (size_t)(n * 64 + cp) * 64;
    float a = 0.f;
#pragma unroll 8
    for (int c = 0; c < 64; c++) a = fmaf(wr[c], ts[c], a);
    g_op[bn * 64 + cp] = a + wb[n * 64 + cp] * (float)HWC;
}

// ---------------- 3a: opn, u = W^T opn; zero g_v ----------------
__global__ void k_u(const float* __restrict__ ww) {
    int bn = blockIdx.x; int n = bn & 15; int c = threadIdx.x;
    __shared__ float opn[64]; __shared__ float red[64];
    float o = g_op[bn * 64 + c];
    red[c] = o * o; __syncthreads();
#pragma unroll
    for (int s = 32; s > 0; s >>= 1) { if (c < s) red[c] += red[c + s]; __syncthreads(); }
    float nrm = fmaxf(sqrtf(red[0]), 1e-12f);
    opn[c] = o / nrm;
    __syncthreads();
    float u = 0.f;
    for (int cp = 0; cp < 64; cp++) u = fmaf(ww[(size_t)(n * 64 + cp) * 64 + c], opn[cp], u);
    g_u[bn * 64 + c] = u;
    g_v[bn * 64 + c] = 0.f;
}

// ---------------- 3b: logits[b,n,hw] = sum_c u[b,n,c]*sr[b,c,hw] ----------------
__global__ void k_logits(const float* __restrict__ sr) {
    int b = blockIdx.y;
    int hw = blockIdx.x * 256 + threadIdx.x;
    __shared__ float us[1024];
    for (int i = threadIdx.x; i < 1024; i += 256) us[i] = g_u[b * 1024 + i];
    __syncthreads();
    float acc[16];
#pragma unroll
    for (int n = 0; n < 16; n++) acc[n] = 0.f;
    const float* sp = sr + (size_t)b * 64 * HWC + hw;
    for (int c = 0; c < 64; c++) {
        float v = sp[(size_t)c * HWC];
#pragma unroll
        for (int n = 0; n < 16; n++) acc[n] = fmaf(us[n * 64 + c], v, acc[n]);
    }
#pragma unroll
    for (int n = 0; n < 16; n++) g_logits[(size_t)(b * 16 + n) * HWC + hw] = acc[n];
}

// ---------------- 3c: softmax over hw (optionally also to d_out cof) ----------------
__global__ void k_softmax(float* extra) {
    int bn = blockIdx.x;
    const float* l = g_logits + (size_t)bn * HWC;
    __shared__ float red[256];
    float mx = -1e30f;
    for (int i = threadIdx.x; i < HWC; i += 256) mx = fmaxf(mx, l[i]);
    mx = bmax256(mx, red);
    float se = 0.f;
    for (int i = threadIdx.x; i < HWC; i += 256) se += expf(l[i] - mx);
    se = bsum256(se, red);
    float inv = 1.f / se;
    float* cf = g_cof + (size_t)bn * HWC;
    float* ex = extra ? extra + (size_t)bn * HWC : nullptr;
    for (int i = threadIdx.x; i < HWC; i += 256) {
        float c = expf(l[i] - mx) * inv;
        cf[i] = c;
        if (ex) ex[i] = c;
    }
}

// ---------------- 3d: v[b,n,c] = sum_hw sr[b,c,hw]*cof[b,n,hw] ----------------
__global__ void k_v(const float* __restrict__ sr) {
    int ch = blockIdx.x;   // 16 chunks of 576 pixels
    int b  = blockIdx.y;
    int hw0 = ch * 576;
    __shared__ float cof_s[16 * 576];
    for (int idx = threadIdx.x; idx < 9216; idx += 256) {
        int n = idx / 576, k = idx - n * 576;
        cof_s[n * 576 + k] = g_cof[(size_t)(b * 16 + n) * HWC + hw0 + k];
    }
    __syncthreads();
    int w = threadIdx.x >> 5, lane = threadIdx.x & 31;
    for (int c = w; c < 64; c += 8) {
        const float* sp = sr + (size_t)(b * 64 + c) * HWC + hw0;
        float a[16];
#pragma unroll
        for (int n = 0; n < 16; n++) a[n] = 0.f;
        for (int k = lane; k < 576; k += 32) {
            float s = sp[k];
#pragma unroll
            for (int n = 0; n < 16; n++) a[n] = fmaf(s, cof_s[n * 576 + k], a[n]);
        }
#pragma unroll
        for (int n = 0; n < 16; n++) {
            float r = wred(a[n]);
            if (lane == 0) atomicAdd(&g_v[(b * 16 + n) * 64 + c], r);
        }
    }
}

// ---------------- 3e: op = W v + w_b ----------------
__global__ void k_op(const float* __restrict__ ww, const float* __restrict__ wb) {
    int bn = blockIdx.x; int n = bn & 15; int cp = threadIdx.x;
    __shared__ float vs[64];
    vs[cp] = g_v[bn * 64 + cp];
    __syncthreads();
    const float* wr = ww + (size_t)(n * 64 + cp) * 64;
    float a = 0.f;
#pragma unroll 8
    for (int c = 0; c < 64; c++) a = fmaf(wr[c], vs[c], a);
    g_op[bn * 64 + cp] = a + wb[n * 64 + cp];
}

// ---------------- 4: analytic GN1 affine; zero GN2 accumulators ----------------
__global__ void k_gn1AD(const float* __restrict__ g1g, const float* __restrict__ g1b) {
    int bn = blockIdx.x; int b = bn >> 4; int c = threadIdx.x;
    float op = g_op[bn * 64 + c];
    float t1 = g_T1[b * 64 + c], t2 = g_T2[b * 64 + c];
    float s1 = t1 + 9216.f * op;
    float s2 = t2 + 2.f * op * t1 + 9216.f * op * op;
    s1 += __shfl_xor_sync(0xffffffffu, s1, 1); s1 += __shfl_xor_sync(0xffffffffu, s1, 2);
    s2 += __shfl_xor_sync(0xffffffffu, s2, 1); s2 += __shfl_xor_sync(0xffffffffu, s2, 2);
    float mu  = s1 * (1.f / 36864.f);
    float var = s2 * (1.f / 36864.f) - mu * mu;
    float inv = rsqrtf(var + EPSN);
    g_A1[bn * 64 + c] = g1g[c] * inv;
    g_D1[bn * 64 + c] = (op - mu) * inv * g1g[c] + g1b[c];
    g_gn2s[bn * 64 + c] = 0.f; g_gn2q[bn * 64 + c] = 0.f;
}

// ---------------- 5: fused GN1+ReLU+conv3x3(64->64) via mma.sync tf32 ----------------
// Block: 256 thr (8 warps). Output tile: 64 co x 256 px (16x16 spatial).
// Warp w: m-strip = w&3 (16 co), n-half = w>>2 (128 px = 16 n8-tiles).
// K = 576 processed in 8 chunks of 72 (8 cin x 9 taps) = 9 k8-steps each.
// Implicit im2col: B[k][px] = in_s[koff[k] + pxoff[px]] (shared row width 19).
__global__ void __launch_bounds__(256, 2) k_conv1(const float* __restrict__ tg,
                                                  const float* __restrict__ c1w,
                                                  const float* __restrict__ c1b) {
    int bn = blockIdx.z, b = bn >> 4;
    int gx0 = blockIdx.x * 16, gy0 = blockIdx.y * 16;
    int tid = threadIdx.x;
    int warp = tid >> 5, lane = tid & 31;
    int gid = lane >> 2, tg4 = lane & 3;
    int mstrip = warp & 3, nhalf = warp >> 2;

    __shared__ float in_s[8 * 342];   // 8 cin x 18 rows x 19 cols (pad)
    __shared__ float w_s[72 * 65];    // stride 65 to dodge A-frag bank conflicts
    __shared__ int   koff[72];
    __shared__ float As[64], Ds[64], Bs[64];

    if (tid < 64) { As[tid] = g_A1[bn * 64 + tid]; Ds[tid] = g_D1[bn * 64 + tid]; Bs[tid] = c1b[tid]; }
    if (tid < 72) {
        int cin = tid / 9, tap = tid - cin * 9;
        koff[tid] = cin * 342 + (tap / 3) * 19 + (tap % 3);
    }

    float acc[16][4];
#pragma unroll
    for (int t = 0; t < 16; t++) { acc[t][0] = 0.f; acc[t][1] = 0.f; acc[t][2] = 0.f; acc[t][3] = 0.f; }

    int pxo[16];
#pragma unroll
    for (int t = 0; t < 16; t++) {
        int n = nhalf * 128 + t * 8 + gid;
        pxo[t] = (n >> 4) * 19 + (n & 15);
    }

    const float* tgb = tg + (size_t)b * 64 * HWC;

    for (int cc = 0; cc < 64; cc += 8) {
        __syncthreads();
        // input halo tile: GN1 affine + ReLU + tf32 round
        for (int idx = tid; idx < 8 * 324; idx += 256) {
            int cin = idx / 324, rem = idx - cin * 324, rr = rem / 18, c2 = rem - rr * 18;
            int gy = gy0 + rr - 1, gx = gx0 + c2 - 1;
            float v = 0.f;
            int ch = cc + cin;
            if ((unsigned)gy < 96u && (unsigned)gx < 96u) {
                float t2 = tgb[(size_t)ch * HWC + gy * 96 + gx];
                v = fmaxf(fmaf(t2, As[ch], Ds[ch]), 0.f);
            }
            in_s[cin * 342 + rr * 19 + c2] = __uint_as_float(f2tf32(v));
        }
        // weights: [klocal][co], tf32
        for (int idx = tid; idx < 4608; idx += 256) {
            int k = idx >> 6, co = idx & 63;
            int cin = k / 9, tap = k - cin * 9;
            float wv = c1w[(size_t)(co * 64 + cc + cin) * 9 + tap];
            w_s[k * 65 + co] = __uint_as_float(f2tf32(wv));
        }
        __syncthreads();
#pragma unroll
        for (int ks = 0; ks < 9; ks++) {
            int k0 = ks * 8 + tg4;
            int row0 = mstrip * 16 + gid;
            uint32_t a0 = __float_as_uint(w_s[k0 * 65 + row0]);
            uint32_t a1 = __float_as_uint(w_s[k0 * 65 + row0 + 8]);
            uint32_t a2 = __float_as_uint(w_s[(k0 + 4) * 65 + row0]);
            uint32_t a3 = __float_as_uint(w_s[(k0 + 4) * 65 + row0 + 8]);
            int ko0 = koff[k0], ko1 = koff[k0 + 4];
#pragma unroll
            for (int t = 0; t < 16; t++) {
                uint32_t b0 = __float_as_uint(in_s[ko0 + pxo[t]]);
                uint32_t b1 = __float_as_uint(in_s[ko1 + pxo[t]]);
                asm volatile("mma.sync.aligned.m16n8k8.row.col.f32.tf32.tf32.f32 "
                             "{%0,%1,%2,%3}, {%4,%5,%6,%7}, {%8,%9}, {%0,%1,%2,%3};"
                             : "+f"(acc[t][0]), "+f"(acc[t][1]), "+f"(acc[t][2]), "+f"(acc[t][3])
                             : "r"(a0), "r"(a1), "r"(a2), "r"(a3), "r"(b0), "r"(b1));
            }
        }
    }

    // epilogue: bias, store y1, GN2 stats
    int co0 = mstrip * 16 + gid;
    float b0v = Bs[co0], b1v = Bs[co0 + 8];
    float s0 = 0.f, q0 = 0.f, s1 = 0.f, q1 = 0.f;
    float* yb0 = g_y1 + (size_t)(bn * 64 + co0) * HWC;
    float* yb1 = g_y1 + (size_t)(bn * 64 + co0 + 8) * HWC;
#pragma unroll
    for (int t = 0; t < 16; t++) {
        int n = nhalf * 128 + t * 8 + 2 * tg4;
        int r = n >> 4, c = n & 15;
        size_t po = (size_t)(gy0 + r) * 96 + gx0 + c;
        float v00 = acc[t][0] + b0v, v01 = acc[t][1] + b0v;
        float v10 = acc[t][2] + b1v, v11 = acc[t][3] + b1v;
        yb0[po] = v00; yb0[po + 1] = v01;
        yb1[po] = v10; yb1[po + 1] = v11;
        s0 += v00 + v01; q0 += v00 * v00 + v01 * v01;
        s1 += v10 + v11; q1 += v10 * v10 + v11 * v11;
    }
    s0 += __shfl_xor_sync(0xffffffffu, s0, 1); s0 += __shfl_xor_sync(0xffffffffu, s0, 2);
    q0 += __shfl_xor_sync(0xffffffffu, q0, 1); q0 += __shfl_xor_sync(0xffffffffu, q0, 2);
    s1 += __shfl_xor_sync(0xffffffffu, s1, 1); s1 += __shfl_xor_sync(0xffffffffu, s1, 2);
    q1 += __shfl_xor_sync(0xffffffffu, q1, 1); q1 += __shfl_xor_sync(0xffffffffu, q1, 2);
    if (tg4 == 0) {
        atomicAdd(&g_gn2s[bn * 64 + co0], s0);     atomicAdd(&g_gn2q[bn * 64 + co0], q0);
        atomicAdd(&g_gn2s[bn * 64 + co0 + 8], s1); atomicAdd(&g_gn2q[bn * 64 + co0 + 8], q1);
    }
}

// ---------------- 6: GN2 affine params (reuse g_A1/g_D1) ----------------
__global__ void k_gn2fin(const float* __restrict__ g2g, const float* __restrict__ g2b) {
    int bn = blockIdx.x, c = threadIdx.x;
    float s = g_gn2s[bn * 64 + c], q = g_gn2q[bn * 64 + c];
    s += __shfl_xor_sync(0xffffffffu, s, 1); s += __shfl_xor_sync(0xffffffffu, s, 2);
    q += __shfl_xor_sync(0xffffffffu, q, 1); q += __shfl_xor_sync(0xffffffffu, q, 2);
    float mu = s * (1.f / 36864.f), var = q * (1.f / 36864.f) - mu * mu;
    float inv = rsqrtf(var + EPSN);
    g_A1[bn * 64 + c] = g2g[c] * inv;
    g_D1[bn * 64 + c] = g2b[c] - mu * inv * g2g[c];
}

// ---------------- 7: fused GN2+ReLU+conv3x3(64->1) -> msk (8-ch chunks) --------
__global__ void __launch_bounds__(256) k_conv2(const float* __restrict__ c2w,
                                               const float* __restrict__ c2b,
                                               float* __restrict__ msk) {
    int bn = blockIdx.z; int gy0 = blockIdx.y * 16, gx0 = blockIdx.x * 16;
    int t = threadIdx.x, ty = t >> 4, tx = t & 15;
    __shared__ float tile[8 * 324];   // 8ch x 18x18
    __shared__ float w2[576];
    __shared__ float A[64], D[64];
    for (int i = t; i < 576; i += 256) w2[i] = c2w[i];
    if (t < 64) { A[t] = g_A1[bn * 64 + t]; D[t] = g_D1[bn * 64 + t]; }
    float acc = c2b[0];
    const float* y = g_y1 + (size_t)bn * 64 * HWC;
    for (int cc = 0; cc < 64; cc += 8) {
        __syncthreads();
        for (int idx = t; idx < 2592; idx += 256) {
            int ch = idx / 324, rem = idx - ch * 324, r = rem / 18, c = rem - r * 18;
            int gy = gy0 + r - 1, gx = gx0 + c - 1;
            float v = 0.f;
            if ((unsigned)gy < 96u && (unsigned)gx < 96u)
                v = fmaxf(fmaf(y[(size_t)(cc + ch) * HWC + gy * 96 + gx], A[cc + ch], D[cc + ch]), 0.f);
            tile[idx] = v;
        }
        __syncthreads();
#pragma unroll
        for (int ch = 0; ch < 8; ch++)
#pragma unroll
            for (int kr = 0; kr < 3; kr++)
#pragma unroll
                for (int kc = 0; kc < 3; kc++)
                    acc = fmaf(w2[(cc + ch) * 9 + kr * 3 + kc],
                               tile[ch * 324 + (ty + kr) * 18 + tx + kc], acc);
    }
    msk[(size_t)bn * HWC + (gy0 + ty) * 96 + gx0 + tx] = acc;
}

// ---------------- 8: per-bn softmax of msk, center loss, IN1 stats ----------------
__global__ void k_msk_stats(const float* __restrict__ msk) {
    int bn = blockIdx.x; int t = threadIdx.x;
    const float* m = msk + (size_t)bn * HWC;
    __shared__ float red[256];
    float mx = -1e30f;
    for (int i = t; i < HWC; i += 256) mx = fmaxf(mx, m[i]);
    mx = bmax256(mx, red);
    float se = 0.f, s1 = 0.f, s2 = 0.f;
    for (int i = t; i < HWC; i += 256) { float v = m[i]; se += expf(v - mx); s1 += v; s2 += v * v; }
    se = bsum256(se, red); s1 = bsum256(s1, red); s2 = bsum256(s2, red);
    float inv_se = 1.f / se;
    float ey = 0.f, ex = 0.f, ey2 = 0.f, ex2 = 0.f;
    const float st = 2.f / 95.f;
    for (int i = t; i < HWC; i += 256) {
        float c = expf(m[i] - mx) * inv_se;
        int ii = i / 96, jj = i - ii * 96;
        float yv = -1.f + st * ii, xv = -1.f + st * jj;
        ey += c * yv; ex += c * xv; ey2 += c * yv * yv; ex2 += c * xv * xv;
    }
    ey = bsum256(ey, red); ex = bsum256(ex, red);
    ey2 = bsum256(ey2, red); ex2 = bsum256(ex2, red);
    if (t == 0) {
        g_lossp[bn] = ey2 - ey * ey + ex2 - ex * ex;
        float mu = s1 / 9216.f; float var = s2 / 9216.f - mu * mu;
        g_mstat[2 * bn] = mu; g_mstat[2 * bn + 1] = rsqrtf(var + EPSN);
        g_in2s[bn] = 0.f; g_in2q[bn] = 0.f;
    }
}

// ---------------- 9: centr loss reduction ----------------
__global__ void k_loss(float* out) {
    __shared__ float red[128];
    int t = threadIdx.x;
    red[t] = g_lossp[t]; __syncthreads();
#pragma unroll
    for (int s = 64; s > 0; s >>= 1) { if (t < s) red[t] += red[t + s]; __syncthreads(); }
    if (t == 0) out[0] = red[0] * (1.f / 128.f);
}

// ---------------- 10: IN1+ReLU+1x1 conv (16->16) + IN2 stat accumulation ---------
__global__ void k_gen1(const float* __restrict__ msk, const float* __restrict__ in1g,
                       const float* __restrict__ in1b, const float* __restrict__ c3w,
                       const float* __restrict__ c3b) {
    int b = blockIdx.y; int hw = blockIdx.x * 256 + threadIdx.x;
    int t = threadIdx.x;
    __shared__ float w3[256], b3[16], mus[16], invs[16], g1[16], bb1[16];
    __shared__ float bs_[16], bq_[16];
    if (t < 256) w3[t] = c3w[t];
    if (t < 16) {
        b3[t] = c3b[t]; int bn = b * 16 + t;
        mus[t] = g_mstat[2 * bn]; invs[t] = g_mstat[2 * bn + 1];
        g1[t] = in1g[t]; bb1[t] = in1b[t]; bs_[t] = 0.f; bq_[t] = 0.f;
    }
    __syncthreads();
    float r[16];
#pragma unroll
    for (int n = 0; n < 16; n++) {
        float m = msk[(size_t)(b * 16 + n) * HWC + hw];
        r[n] = fmaxf((m - mus[n]) * invs[n] * g1[n] + bb1[n], 0.f);
    }
#pragma unroll
    for (int o = 0; o < 16; o++) {
        float a = b3[o];
#pragma unroll
        for (int n = 0; n < 16; n++) a = fmaf(w3[o * 16 + n], r[n], a);
        g_g2[(size_t)(b * 16 + o) * HWC + hw] = a;
        float s = wred(a), q = wred(a * a);
        if ((t & 31) == 0) { atomicAdd(&bs_[o], s); atomicAdd(&bq_[o], q); }
    }
    __syncthreads();
    if (t < 16) { atomicAdd(&g_in2s[b * 16 + t], bs_[t]); atomicAdd(&g_in2q[b * 16 + t], bq_[t]); }
}

// ---------------- 11: IN2 stats finalize ----------------
__global__ void k_in2fin() {
    int i = threadIdx.x;
    float mu = g_in2s[i] / 9216.f;
    float var = g_in2q[i] / 9216.f - mu * mu;
    g_in2stat[2 * i] = mu; g_in2stat[2 * i + 1] = rsqrtf(var + EPSN);
}

// ---------------- 12: IN2+ReLU+1x1(16->3)+sigmoid -> rec ----------------
__global__ void k_rec(const float* __restrict__ in2g, const float* __restrict__ in2b,
                      const float* __restrict__ c4w, const float* __restrict__ c4b,
                      float* __restrict__ out) {
    int b = blockIdx.y; int hw = blockIdx.x * 256 + threadIdx.x; int t = threadIdx.x;
    __shared__ float w4[48], mus[16], invs[16], g2[16], bb2[16];
    if (t < 48) w4[t] = c4w[t];
    if (t < 16) {
        int bo = b * 16 + t;
        mus[t] = g_in2stat[2 * bo]; invs[t] = g_in2stat[2 * bo + 1];
        g2[t] = in2g[t]; bb2[t] = in2b[t];
    }
    __syncthreads();
    float x[16];
#pragma unroll
    for (int o = 0; o < 16; o++) {
        float v = g_g2[(size_t)(b * 16 + o) * HWC + hw];
        x[o] = fmaxf((v - mus[o]) * invs[o] * g2[o] + bb2[o], 0.f);
    }
#pragma unroll
    for (int o2 = 0; o2 < 3; o2++) {
        float a = c4b[o2];
#pragma unroll
        for (int o = 0; o < 16; o++) a = fmaf(w4[o2 * 16 + o], x[o], a);
        out[(size_t)(b * 3 + o2) * HWC + hw] = 1.f / (1.f + expf(-a));
    }
}

// ---------------- 13: op_out = op[bnc] * msk[bn,hw] ----------------
__global__ void k_opout(const float* __restrict__ msk, float* __restrict__ out) {
    int bn = blockIdx.y; int hw = blockIdx.x * 256 + threadIdx.x;
    __shared__ float ops[64];
    if (threadIdx.x < 64) ops[threadIdx.x] = g_op[bn * 64 + threadIdx.x];
    __syncthreads();
    float m = msk[(size_t)bn * HWC + hw];
    float* o = out + (size_t)bn * 64 * HWC + hw;
#pragma unroll 8
    for (int c = 0; c < 64; c++) o[(size_t)c * HWC] = ops[c] * m;
}

// ---------------- launch ----------------
extern "C" void kernel_launch(void* const* d_in, const int* in_sizes, int n_in,
                              void* d_out, int out_size) {
    const float* sr   = (const float*)d_in[0];
    const float* tg   = (const float*)d_in[1];
    const float* ww   = (const float*)d_in[2];
    const float* wb   = (const float*)d_in[3];
    const float* gn1g = (const float*)d_in[4];
    const float* gn1b = (const float*)d_in[5];
    const float* c1w  = (const float*)d_in[6];
    const float* c1b  = (const float*)d_in[7];
    const float* gn2g = (const float*)d_in[8];
    const float* gn2b = (const float*)d_in[9];
    const float* c2w  = (const float*)d_in[10];
    const float* c2b  = (const float*)d_in[11];
    const float* in1g = (const float*)d_in[12];
    const float* in1b = (const float*)d_in[13];
    const float* c3w  = (const float*)d_in[14];
    const float* c3b  = (const float*)d_in[15];
    const float* in2g = (const float*)d_in[16];
    const float* in2b = (const float*)d_in[17];
    const float* c4w  = (const float*)d_in[18];
    const float* c4b  = (const float*)d_in[19];
    float* out = (float*)d_out;
    float* out_msk  = out + 75497472;
    float* out_rec  = out + 76677120;
    float* out_loss = out + 76898304;
    float* out_cof  = out + 76898305;

    k_colsum<<<512, 256>>>(sr, tg);
    k_op0<<<128, 64>>>(ww, wb);
    for (int it = 0; it < 3; it++) {
        k_u<<<128, 64>>>(ww);
        k_logits<<<dim3(36, 8), 256>>>(sr);
        k_softmax<<<128, 256>>>(it == 2 ? out_cof : (float*)nullptr);
        k_v<<<dim3(16, 8), 256>>>(sr);
        k_op<<<128, 64>>>(ww, wb);
    }
    k_gn1AD<<<128, 64>>>(gn1g, gn1b);
    k_conv1<<<dim3(6, 6, 128), 256>>>(tg, c1w, c1b);
    k_gn2fin<<<128, 64>>>(gn2g, gn2b);
    k_conv2<<<dim3(6, 6, 128), 256>>>(c2w, c2b, out_msk);
    k_msk_stats<<<128, 256>>>(out_msk);
    k_loss<<<1, 128>>>(out_loss);
    k_gen1<<<dim3(36, 8), 256>>>(out_msk, in1g, in1b, c3w, c3b);
    k_in2fin<<<1, 128>>>();
    k_rec<<<dim3(36, 8), 256>>>(in2g, in2b, c4w, c4b, out_rec);
    k_opout<<<dim3(36, 128), 256>>>(out_msk, out);
}

// round 4
// speedup vs baseline: 1.9773x; 1.0855x over previous
#include <cuda_runtime.h>
#include <cuda_fp16.h>
#include <cstdint>
#include <cstddef>

#define HWC 9216
#define EPSN 1e-5f

// ---------------- scratch (__device__ globals; no allocation) ----------------
__device__ float g_y1[75497472];      // conv1 output [128,64,9216]
__device__ float g_logits[1179648];   // [128,9216]
__device__ float g_cof[1179648];      // [128,9216]
__device__ float g_g2[1179648];       // gen-block intermediate [8,16,9216]
__device__ float g_tsum[512];         // sum_hw sr [8,64]
__device__ float g_T1[512];           // sum_hw tg
__device__ float g_T2[512];           // sum_hw tg^2
__device__ float g_op[8192];          // [128,64]
__device__ float g_u[8192];           // W^T opn
__device__ float g_v[8192];           // sum_hw sr*cof
__device__ float g_A1[8192];          // GN affine scale (reused GN1 then GN2)
__device__ float g_D1[8192];          // GN affine shift
__device__ float g_gn2s[8192];        // per-channel sums for GN2
__device__ float g_gn2q[8192];
__device__ float g_mstat[256];        // per-bn (mu, invstd) of msk for IN1
__device__ float g_in2s[128];
__device__ float g_in2q[128];
__device__ float g_in2stat[256];
__device__ float g_lossp[128];

// ---------------- helpers ----------------
__device__ __forceinline__ float wred(float v) {
#pragma unroll
    for (int o = 16; o > 0; o >>= 1) v += __shfl_xor_sync(0xffffffffu, v, o);
    return v;
}
__device__ __forceinline__ float bsum256(float v, float* red) {
    int t = threadIdx.x; red[t] = v; __syncthreads();
#pragma unroll
    for (int s = 128; s > 0; s >>= 1) { if (t < s) red[t] += red[t + s]; __syncthreads(); }
    float r = red[0]; __syncthreads(); return r;
}
__device__ __forceinline__ float bmax256(float v, float* red) {
    int t = threadIdx.x; red[t] = v; __syncthreads();
#pragma unroll
    for (int s = 128; s > 0; s >>= 1) { if (t < s) red[t] = fmaxf(red[t], red[t + s]); __syncthreads(); }
    float r = red[0]; __syncthreads(); return r;
}
// cin-slot permutation: slots 4p..4p+3 hold cins {2p,2p+1,2p+8,2p+9}
__device__ __forceinline__ int cin_slot(int cin) {
    int p = (cin & 7) >> 1;
    int pos = ((cin >> 3) << 1) | (cin & 1);
    return 4 * p + pos;
}

// ---------------- 1: per-(b,c) sums of sr / tg / tg^2 ----------------
__global__ void k_colsum(const float* __restrict__ sr, const float* __restrict__ tg) {
    int bc = blockIdx.x;
    const float* ps = sr + (size_t)bc * HWC;
    const float* pt = tg + (size_t)bc * HWC;
    float s0 = 0.f, s1 = 0.f, s2 = 0.f;
    for (int i = threadIdx.x; i < HWC; i += 256) {
        s0 += ps[i];
        float t = pt[i]; s1 += t; s2 += t * t;
    }
    __shared__ float red[256];
    s0 = bsum256(s0, red); s1 = bsum256(s1, red); s2 = bsum256(s2, red);
    if (threadIdx.x == 0) { g_tsum[bc] = s0; g_T1[bc] = s1; g_T2[bc] = s2; }
}

// ---------------- 2: op0 = W * colsum(sr) + w_b * HW ----------------
__global__ void k_op0(const float* __restrict__ ww, const float* __restrict__ wb) {
    int bn = blockIdx.x; int b = bn >> 4, n = bn & 15; int cp = threadIdx.x;
    __shared__ float ts[64];
    ts[cp] = g_tsum[b * 64 + cp];
    __syncthreads();
    const float* wr = ww + (size_t)(n * 64 + cp) * 64;
    float a = 0.f;
#pragma unroll 8
    for (int c = 0; c < 64; c++) a = fmaf(wr[c], ts[c], a);
    g_op[bn * 64 + cp] = a + wb[n * 64 + cp] * (float)HWC;
}

// ---------------- 3a: opn, u = W^T opn; zero g_v ----------------
__global__ void k_u(const float* __restrict__ ww) {
    int bn = blockIdx.x; int n = bn & 15; int c = threadIdx.x;
    __shared__ float opn[64]; __shared__ float red[64];
    float o = g_op[bn * 64 + c];
    red[c] = o * o; __syncthreads();
#pragma unroll
    for (int s = 32; s > 0; s >>= 1) { if (c < s) red[c] += red[c + s]; __syncthreads(); }
    float nrm = fmaxf(sqrtf(red[0]), 1e-12f);
    opn[c] = o / nrm;
    __syncthreads();
    float u = 0.f;
    for (int cp = 0; cp < 64; cp++) u = fmaf(ww[(size_t)(n * 64 + cp) * 64 + c], opn[cp], u);
    g_u[bn * 64 + c] = u;
    g_v[bn * 64 + c] = 0.f;
}

// ---------------- 3b: logits[b,n,hw] = sum_c u[b,n,c]*sr[b,c,hw] ----------------
__global__ void k_logits(const float* __restrict__ sr) {
    int b = blockIdx.y;
    int hw = blockIdx.x * 256 + threadIdx.x;
    __shared__ float us[1024];
    for (int i = threadIdx.x; i < 1024; i += 256) us[i] = g_u[b * 1024 + i];
    __syncthreads();
    float acc[16];
#pragma unroll
    for (int n = 0; n < 16; n++) acc[n] = 0.f;
    const float* sp = sr + (size_t)b * 64 * HWC + hw;
    for (int c = 0; c < 64; c++) {
        float v = sp[(size_t)c * HWC];
#pragma unroll
        for (int n = 0; n < 16; n++) acc[n] = fmaf(us[n * 64 + c], v, acc[n]);
    }
#pragma unroll
    for (int n = 0; n < 16; n++) g_logits[(size_t)(b * 16 + n) * HWC + hw] = acc[n];
}

// ---------------- 3c: softmax over hw (optionally also to d_out cof) ----------------
__global__ void k_softmax(float* extra) {
    int bn = blockIdx.x;
    const float* l = g_logits + (size_t)bn * HWC;
    __shared__ float red[256];
    float mx = -1e30f;
    for (int i = threadIdx.x; i < HWC; i += 256) mx = fmaxf(mx, l[i]);
    mx = bmax256(mx, red);
    float se = 0.f;
    for (int i = threadIdx.x; i < HWC; i += 256) se += expf(l[i] - mx);
    se = bsum256(se, red);
    float inv = 1.f / se;
    float* cf = g_cof + (size_t)bn * HWC;
    float* ex = extra ? extra + (size_t)bn * HWC : nullptr;
    for (int i = threadIdx.x; i < HWC; i += 256) {
        float c = expf(l[i] - mx) * inv;
        cf[i] = c;
        if (ex) ex[i] = c;
    }
}

// ---------------- 3d: v[b,n,c] = sum_hw sr[b,c,hw]*cof[b,n,hw] ----------------
__global__ void k_v(const float* __restrict__ sr) {
    int ch = blockIdx.x;   // 16 chunks of 576 pixels
    int b  = blockIdx.y;
    int hw0 = ch * 576;
    __shared__ float cof_s[16 * 576];
    for (int idx = threadIdx.x; idx < 9216; idx += 256) {
        int n = idx / 576, k = idx - n * 576;
        cof_s[n * 576 + k] = g_cof[(size_t)(b * 16 + n) * HWC + hw0 + k];
    }
    __syncthreads();
    int w = threadIdx.x >> 5, lane = threadIdx.x & 31;
    for (int c = w; c < 64; c += 8) {
        const float* sp = sr + (size_t)(b * 64 + c) * HWC + hw0;
        float a[16];
#pragma unroll
        for (int n = 0; n < 16; n++) a[n] = 0.f;
        for (int k = lane; k < 576; k += 32) {
            float s = sp[k];
#pragma unroll
            for (int n = 0; n < 16; n++) a[n] = fmaf(s, cof_s[n * 576 + k], a[n]);
        }
#pragma unroll
        for (int n = 0; n < 16; n++) {
            float r = wred(a[n]);
            if (lane == 0) atomicAdd(&g_v[(b * 16 + n) * 64 + c], r);
        }
    }
}

// ---------------- 3e: op = W v + w_b ----------------
__global__ void k_op(const float* __restrict__ ww, const float* __restrict__ wb) {
    int bn = blockIdx.x; int n = bn & 15; int cp = threadIdx.x;
    __shared__ float vs[64];
    vs[cp] = g_v[bn * 64 + cp];
    __syncthreads();
    const float* wr = ww + (size_t)(n * 64 + cp) * 64;
    float a = 0.f;
#pragma unroll 8
    for (int c = 0; c < 64; c++) a = fmaf(wr[c], vs[c], a);
    g_op[bn * 64 + cp] = a + wb[n * 64 + cp];
}

// ---------------- 4: analytic GN1 affine; zero GN2 accumulators ----------------
__global__ void k_gn1AD(const float* __restrict__ g1g, const float* __restrict__ g1b) {
    int bn = blockIdx.x; int b = bn >> 4; int c = threadIdx.x;
    float op = g_op[bn * 64 + c];
    float t1 = g_T1[b * 64 + c], t2 = g_T2[b * 64 + c];
    float s1 = t1 + 9216.f * op;
    float s2 = t2 + 2.f * op * t1 + 9216.f * op * op;
    s1 += __shfl_xor_sync(0xffffffffu, s1, 1); s1 += __shfl_xor_sync(0xffffffffu, s1, 2);
    s2 += __shfl_xor_sync(0xffffffffu, s2, 1); s2 += __shfl_xor_sync(0xffffffffu, s2, 2);
    float mu  = s1 * (1.f / 36864.f);
    float var = s2 * (1.f / 36864.f) - mu * mu;
    float inv = rsqrtf(var + EPSN);
    g_A1[bn * 64 + c] = g1g[c] * inv;
    g_D1[bn * 64 + c] = (op - mu) * inv * g1g[c] + g1b[c];
    g_gn2s[bn * 64 + c] = 0.f; g_gn2q[bn * 64 + c] = 0.f;
}

// ---------------- 5: fused GN1+ReLU+conv3x3(64->64) via mma.m16n8k16 fp16 --------
// Block 256 thr (8 warps). Tile: 64 co x 256 px (16x16 spatial).
// Warp: mgroup = w&1 (32 co = 2 m16 strips), ngroup = w>>1 (64 px = 8 n8 tiles).
// K ordering: 4 chunks of 16 cin; within chunk k = tap*16 + cin (9 k16-steps,
// one tap per step). cin-slot permutation makes every A/B fragment one LDS.64.
// in_s: channel-last [spatial 18x18][16 cin-slots] half.
// w_s: [tap][co][16 cin-slots] half.
__global__ void __launch_bounds__(256, 2) k_conv1(const float* __restrict__ tg,
                                                  const float* __restrict__ c1w,
                                                  const float* __restrict__ c1b) {
    int bn = blockIdx.z, b = bn >> 4;
    int gx0 = blockIdx.x * 16, gy0 = blockIdx.y * 16;
    int tid = threadIdx.x;
    int warp = tid >> 5, lane = tid & 31;
    int gid = lane >> 2, tg4 = lane & 3;
    int mgroup = warp & 1, ngroup = warp >> 1;

    __shared__ __half in_s[324 * 16];     // 10368 B
    __shared__ __half w_s[9 * 64 * 16];   // 18432 B
    __shared__ float As[64], Ds[64], Bs[64];

    if (tid < 64) { As[tid] = g_A1[bn * 64 + tid]; Ds[tid] = g_D1[bn * 64 + tid]; Bs[tid] = c1b[tid]; }

    float acc[2][8][4];
#pragma unroll
    for (int s = 0; s < 2; s++)
#pragma unroll
        for (int t = 0; t < 8; t++) { acc[s][t][0] = 0.f; acc[s][t][1] = 0.f; acc[s][t][2] = 0.f; acc[s][t][3] = 0.f; }

    int sidx[8];
#pragma unroll
    for (int t = 0; t < 8; t++) {
        int n = ngroup * 64 + t * 8 + gid;
        sidx[t] = (n >> 4) * 18 + (n & 15);
    }

    const float* tgb = tg + (size_t)b * 64 * HWC;

    for (int cc = 0; cc < 64; cc += 16) {
        __syncthreads();
        // input halo tile fill: GN1 affine + ReLU -> half, channel-last w/ slot perm
        for (int idx = tid; idx < 5184; idx += 256) {
            int cin = idx / 324, sp = idx - cin * 324;
            int rr = sp / 18, c2 = sp - rr * 18;
            int gy = gy0 + rr - 1, gx = gx0 + c2 - 1;
            float v = 0.f;
            int ch = cc + cin;
            if ((unsigned)gy < 96u && (unsigned)gx < 96u) {
                float t2 = tgb[(size_t)ch * HWC + gy * 96 + gx];
                v = fmaxf(fmaf(t2, As[ch], Ds[ch]), 0.f);
            }
            in_s[sp * 16 + cin_slot(cin)] = __float2half_rn(v);
        }
        // weights fill
        for (int idx = tid; idx < 9216; idx += 256) {
            int co = idx & 63, kk = idx >> 6;
            int cin = kk & 15, tap = kk >> 4;
            float wv = c1w[(size_t)(co * 64 + cc + cin) * 9 + tap];
            w_s[(tap * 64 + co) * 16 + cin_slot(cin)] = __float2half_rn(wv);
        }
        __syncthreads();
#pragma unroll
        for (int ks = 0; ks < 9; ks++) {
            int toff = (ks / 3) * 18 + (ks % 3);
            uint2 afr[2][2];
#pragma unroll
            for (int s = 0; s < 2; s++) {
                int co_r0 = mgroup * 32 + s * 16 + gid;
                afr[s][0] = *(const uint2*)(w_s + (ks * 64 + co_r0) * 16 + tg4 * 4);
                afr[s][1] = *(const uint2*)(w_s + (ks * 64 + co_r0 + 8) * 16 + tg4 * 4);
            }
#pragma unroll
            for (int t = 0; t < 8; t++) {
                uint2 bb = *(const uint2*)(in_s + (toff + sidx[t]) * 16 + tg4 * 4);
#pragma unroll
                for (int s = 0; s < 2; s++) {
                    asm volatile("mma.sync.aligned.m16n8k16.row.col.f32.f16.f16.f32 "
                                 "{%0,%1,%2,%3}, {%4,%5,%6,%7}, {%8,%9}, {%0,%1,%2,%3};"
                                 : "+f"(acc[s][t][0]), "+f"(acc[s][t][1]),
                                   "+f"(acc[s][t][2]), "+f"(acc[s][t][3])
                                 : "r"(afr[s][0].x), "r"(afr[s][1].x),
                                   "r"(afr[s][0].y), "r"(afr[s][1].y),
                                   "r"(bb.x), "r"(bb.y));
                }
            }
        }
    }

    // epilogue: bias, store y1, GN2 stats
#pragma unroll
    for (int s = 0; s < 2; s++) {
        int co0 = mgroup * 32 + s * 16 + gid;
        int co1 = co0 + 8;
        float b0v = Bs[co0], b1v = Bs[co1];
        float s0 = 0.f, q0 = 0.f, s1 = 0.f, q1 = 0.f;
        float* yb0 = g_y1 + (size_t)(bn * 64 + co0) * HWC;
        float* yb1 = g_y1 + (size_t)(bn * 64 + co1) * HWC;
#pragma unroll
        for (int t = 0; t < 8; t++) {
            int n = ngroup * 64 + t * 8 + tg4 * 2;
            int r = n >> 4, c = n & 15;
            size_t po = (size_t)(gy0 + r) * 96 + gx0 + c;
            float v00 = acc[s][t][0] + b0v, v01 = acc[s][t][1] + b0v;
            float v10 = acc[s][t][2] + b1v, v11 = acc[s][t][3] + b1v;
            yb0[po] = v00; yb0[po + 1] = v01;
            yb1[po] = v10; yb1[po + 1] = v11;
            s0 += v00 + v01; q0 += v00 * v00 + v01 * v01;
            s1 += v10 + v11; q1 += v10 * v10 + v11 * v11;
        }
        s0 += __shfl_xor_sync(0xffffffffu, s0, 1); s0 += __shfl_xor_sync(0xffffffffu, s0, 2);
        q0 += __shfl_xor_sync(0xffffffffu, q0, 1); q0 += __shfl_xor_sync(0xffffffffu, q0, 2);
        s1 += __shfl_xor_sync(0xffffffffu, s1, 1); s1 += __shfl_xor_sync(0xffffffffu, s1, 2);
        q1 += __shfl_xor_sync(0xffffffffu, q1, 1); q1 += __shfl_xor_sync(0xffffffffu, q1, 2);
        if (tg4 == 0) {
            atomicAdd(&g_gn2s[bn * 64 + co0], s0); atomicAdd(&g_gn2q[bn * 64 + co0], q0);
            atomicAdd(&g_gn2s[bn * 64 + co1], s1); atomicAdd(&g_gn2q[bn * 64 + co1], q1);
        }
    }
}

// ---------------- 6: GN2 affine params (reuse g_A1/g_D1) ----------------
__global__ void k_gn2fin(const float* __restrict__ g2g, const float* __restrict__ g2b) {
    int bn = blockIdx.x, c = threadIdx.x;
    float s = g_gn2s[bn * 64 + c], q = g_gn2q[bn * 64 + c];
    s += __shfl_xor_sync(0xffffffffu, s, 1); s += __shfl_xor_sync(0xffffffffu, s, 2);
    q += __shfl_xor_sync(0xffffffffu, q, 1); q += __shfl_xor_sync(0xffffffffu, q, 2);
    float mu = s * (1.f / 36864.f), var = q * (1.f / 36864.f) - mu * mu;
    float inv = rsqrtf(var + EPSN);
    g_A1[bn * 64 + c] = g2g[c] * inv;
    g_D1[bn * 64 + c] = g2b[c] - mu * inv * g2g[c];
}

// ---------------- 7: fused GN2+ReLU+conv3x3(64->1) -> msk (8-ch chunks) --------
__global__ void __launch_bounds__(256) k_conv2(const float* __restrict__ c2w,
                                               const float* __restrict__ c2b,
                                               float* __restrict__ msk) {
    int bn = blockIdx.z; int gy0 = blockIdx.y * 16, gx0 = blockIdx.x * 16;
    int t = threadIdx.x, ty = t >> 4, tx = t & 15;
    __shared__ float tile[8 * 324];   // 8ch x 18x18
    __shared__ float w2[576];
    __shared__ float A[64], D[64];
    for (int i = t; i < 576; i += 256) w2[i] = c2w[i];
    if (t < 64) { A[t] = g_A1[bn * 64 + t]; D[t] = g_D1[bn * 64 + t]; }
    float acc = c2b[0];
    const float* y = g_y1 + (size_t)bn * 64 * HWC;
    for (int cc = 0; cc < 64; cc += 8) {
        __syncthreads();
        for (int idx = t; idx < 2592; idx += 256) {
            int ch = idx / 324, rem = idx - ch * 324, r = rem / 18, c = rem - r * 18;
            int gy = gy0 + r - 1, gx = gx0 + c - 1;
            float v = 0.f;
            if ((unsigned)gy < 96u && (unsigned)gx < 96u)
                v = fmaxf(fmaf(y[(size_t)(cc + ch) * HWC + gy * 96 + gx], A[cc + ch], D[cc + ch]), 0.f);
            tile[idx] = v;
        }
        __syncthreads();
#pragma unroll
        for (int ch = 0; ch < 8; ch++)
#pragma unroll
            for (int kr = 0; kr < 3; kr++)
#pragma unroll
                for (int kc = 0; kc < 3; kc++)
                    acc = fmaf(w2[(cc + ch) * 9 + kr * 3 + kc],
                               tile[ch * 324 + (ty + kr) * 18 + tx + kc], acc);
    }
    msk[(size_t)bn * HWC + (gy0 + ty) * 96 + gx0 + tx] = acc;
}

// ---------------- 8: per-bn softmax of msk, center loss, IN1 stats ----------------
__global__ void k_msk_stats(const float* __restrict__ msk) {
    int bn = blockIdx.x; int t = threadIdx.x;
    const float* m = msk + (size_t)bn * HWC;
    __shared__ float red[256];
    float mx = -1e30f;
    for (int i = t; i < HWC; i += 256) mx = fmaxf(mx, m[i]);
    mx = bmax256(mx, red);
    float se = 0.f, s1 = 0.f, s2 = 0.f;
    for (int i = t; i < HWC; i += 256) { float v = m[i]; se += expf(v - mx); s1 += v; s2 += v * v; }
    se = bsum256(se, red); s1 = bsum256(s1, red); s2 = bsum256(s2, red);
    float inv_se = 1.f / se;
    float ey = 0.f, ex = 0.f, ey2 = 0.f, ex2 = 0.f;
    const float st = 2.f / 95.f;
    for (int i = t; i < HWC; i += 256) {
        float c = expf(m[i] - mx) * inv_se;
        int ii = i / 96, jj = i - ii * 96;
        float yv = -1.f + st * ii, xv = -1.f + st * jj;
        ey += c * yv; ex += c * xv; ey2 += c * yv * yv; ex2 += c * xv * xv;
    }
    ey = bsum256(ey, red); ex = bsum256(ex, red);
    ey2 = bsum256(ey2, red); ex2 = bsum256(ex2, red);
    if (t == 0) {
        g_lossp[bn] = ey2 - ey * ey + ex2 - ex * ex;
        float mu = s1 / 9216.f; float var = s2 / 9216.f - mu * mu;
        g_mstat[2 * bn] = mu; g_mstat[2 * bn + 1] = rsqrtf(var + EPSN);
        g_in2s[bn] = 0.f; g_in2q[bn] = 0.f;
    }
}

// ---------------- 9: centr loss reduction ----------------
__global__ void k_loss(float* out) {
    __shared__ float red[128];
    int t = threadIdx.x;
    red[t] = g_lossp[t]; __syncthreads();
#pragma unroll
    for (int s = 64; s > 0; s >>= 1) { if (t < s) red[t] += red[t + s]; __syncthreads(); }
    if (t == 0) out[0] = red[0] * (1.f / 128.f);
}

// ---------------- 10: IN1+ReLU+1x1 conv (16->16) + IN2 stat accumulation ---------
__global__ void k_gen1(const float* __restrict__ msk, const float* __restrict__ in1g,
                       const float* __restrict__ in1b, const float* __restrict__ c3w,
                       const float* __restrict__ c3b) {
    int b = blockIdx.y; int hw = blockIdx.x * 256 + threadIdx.x;
    int t = threadIdx.x;
    __shared__ float w3[256], b3[16], mus[16], invs[16], g1[16], bb1[16];
    __shared__ float bs_[16], bq_[16];
    if (t < 256) w3[t] = c3w[t];
    if (t < 16) {
        b3[t] = c3b[t]; int bn = b * 16 + t;
        mus[t] = g_mstat[2 * bn]; invs[t] = g_mstat[2 * bn + 1];
        g1[t] = in1g[t]; bb1[t] = in1b[t]; bs_[t] = 0.f; bq_[t] = 0.f;
    }
    __syncthreads();
    float r[16];
#pragma unroll
    for (int n = 0; n < 16; n++) {
        float m = msk[(size_t)(b * 16 + n) * HWC + hw];
        r[n] = fmaxf((m - mus[n]) * invs[n] * g1[n] + bb1[n], 0.f);
    }
#pragma unroll
    for (int o = 0; o < 16; o++) {
        float a = b3[o];
#pragma unroll
        for (int n = 0; n < 16; n++) a = fmaf(w3[o * 16 + n], r[n], a);
        g_g2[(size_t)(b * 16 + o) * HWC + hw] = a;
        float s = wred(a), q = wred(a * a);
        if ((t & 31) == 0) { atomicAdd(&bs_[o], s); atomicAdd(&bq_[o], q); }
    }
    __syncthreads();
    if (t < 16) { atomicAdd(&g_in2s[b * 16 + t], bs_[t]); atomicAdd(&g_in2q[b * 16 + t], bq_[t]); }
}

// ---------------- 11: IN2 stats finalize ----------------
__global__ void k_in2fin() {
    int i = threadIdx.x;
    float mu = g_in2s[i] / 9216.f;
    float var = g_in2q[i] / 9216.f - mu * mu;
    g_in2stat[2 * i] = mu; g_in2stat[2 * i + 1] = rsqrtf(var + EPSN);
}

// ---------------- 12: IN2+ReLU+1x1(16->3)+sigmoid -> rec ----------------
__global__ void k_rec(const float* __restrict__ in2g, const float* __restrict__ in2b,
                      const float* __restrict__ c4w, const float* __restrict__ c4b,
                      float* __restrict__ out) {
    int b = blockIdx.y; int hw = blockIdx.x * 256 + threadIdx.x; int t = threadIdx.x;
    __shared__ float w4[48], mus[16], invs[16], g2[16], bb2[16];
    if (t < 48) w4[t] = c4w[t];
    if (t < 16) {
        int bo = b * 16 + t;
        mus[t] = g_in2stat[2 * bo]; invs[t] = g_in2stat[2 * bo + 1];
        g2[t] = in2g[t]; bb2[t] = in2b[t];
    }
    __syncthreads();
    float x[16];
#pragma unroll
    for (int o = 0; o < 16; o++) {
        float v = g_g2[(size_t)(b * 16 + o) * HWC + hw];
        x[o] = fmaxf((v - mus[o]) * invs[o] * g2[o] + bb2[o], 0.f);
    }
#pragma unroll
    for (int o2 = 0; o2 < 3; o2++) {
        float a = c4b[o2];
#pragma unroll
        for (int o = 0; o < 16; o++) a = fmaf(w4[o2 * 16 + o], x[o], a);
        out[(size_t)(b * 3 + o2) * HWC + hw] = 1.f / (1.f + expf(-a));
    }
}

// ---------------- 13: op_out = op[bnc] * msk[bn,hw] ----------------
__global__ void k_opout(const float* __restrict__ msk, float* __restrict__ out) {
    int bn = blockIdx.y; int hw = blockIdx.x * 256 + threadIdx.x;
    __shared__ float ops[64];
    if (threadIdx.x < 64) ops[threadIdx.x] = g_op[bn * 64 + threadIdx.x];
    __syncthreads();
    float m = msk[(size_t)bn * HWC + hw];
    float* o = out + (size_t)bn * 64 * HWC + hw;
#pragma unroll 8
    for (int c = 0; c < 64; c++) o[(size_t)c * HWC] = ops[c] * m;
}

// ---------------- launch ----------------
extern "C" void kernel_launch(void* const* d_in, const int* in_sizes, int n_in,
                              void* d_out, int out_size) {
    const float* sr   = (const float*)d_in[0];
    const float* tg   = (const float*)d_in[1];
    const float* ww   = (const float*)d_in[2];
    const float* wb   = (const float*)d_in[3];
    const float* gn1g = (const float*)d_in[4];
    const float* gn1b = (const float*)d_in[5];
    const float* c1w  = (const float*)d_in[6];
    const float* c1b  = (const float*)d_in[7];
    const float* gn2g = (const float*)d_in[8];
    const float* gn2b = (const float*)d_in[9];
    const float* c2w  = (const float*)d_in[10];
    const float* c2b  = (const float*)d_in[11];
    const float* in1g = (const float*)d_in[12];
    const float* in1b = (const float*)d_in[13];
    const float* c3w  = (const float*)d_in[14];
    const float* c3b  = (const float*)d_in[15];
    const float* in2g = (const float*)d_in[16];
    const float* in2b = (const float*)d_in[17];
    const float* c4w  = (const float*)d_in[18];
    const float* c4b  = (const float*)d_in[19];
    float* out = (float*)d_out;
    float* out_msk  = out + 75497472;
    float* out_rec  = out + 76677120;
    float* out_loss = out + 76898304;
    float* out_cof  = out + 76898305;

    k_colsum<<<512, 256>>>(sr, tg);
    k_op0<<<128, 64>>>(ww, wb);
    for (int it = 0; it < 3; it++) {
        k_u<<<128, 64>>>(ww);
        k_logits<<<dim3(36, 8), 256>>>(sr);
        k_softmax<<<128, 256>>>(it == 2 ? out_cof : (float*)nullptr);
        k_v<<<dim3(16, 8), 256>>>(sr);
        k_op<<<128, 64>>>(ww, wb);
    }
    k_gn1AD<<<128, 64>>>(gn1g, gn1b);
    k_conv1<<<dim3(6, 6, 128), 256>>>(tg, c1w, c1b);
    k_gn2fin<<<128, 64>>>(gn2g, gn2b);
    k_conv2<<<dim3(6, 6, 128), 256>>>(c2w, c2b, out_msk);
    k_msk_stats<<<128, 256>>>(out_msk);
    k_loss<<<1, 128>>>(out_loss);
    k_gen1<<<dim3(36, 8), 256>>>(out_msk, in1g, in1b, c3w, c3b);
    k_in2fin<<<1, 128>>>();
    k_rec<<<dim3(36, 8), 256>>>(in2g, in2b, c4w, c4b, out_rec);
    k_opout<<<dim3(36, 128), 256>>>(out_msk, out);
}

// round 5
// speedup vs baseline: 3.6655x; 1.8538x over previous
#include <cuda_runtime.h>
#include <cuda_fp16.h>
#include <cstdint>
#include <cstddef>

#define HWC 9216
#define EPSN 1e-5f

// ---------------- scratch (__device__ globals; no allocation) ----------------
__device__ float g_y1[75497472];      // conv1 output [128,64,9216]
__device__ float g_logits[1179648];   // [128,9216]
__device__ float g_cof[1179648];      // [128,9216]
__device__ float g_g2[1179648];       // gen-block intermediate [8,16,9216]
__device__ float g_tsum[512];         // sum_hw sr [8,64]
__device__ float g_T1[512];           // sum_hw tg
__device__ float g_T2[512];           // sum_hw tg^2
__device__ float g_op[8192];          // [128,64]
__device__ float g_u[8192];           // W^T opn
__device__ float g_v[8192];           // sum_hw sr*cof
__device__ float g_A1[8192];          // GN affine scale (reused GN1 then GN2)
__device__ float g_D1[8192];          // GN affine shift
__device__ float g_gn2s[8192];        // per-channel sums for GN2
__device__ float g_gn2q[8192];
__device__ float g_mstat[256];        // per-bn (mu, invstd) of msk for IN1
__device__ float g_in2s[128];
__device__ float g_in2q[128];
__device__ float g_in2stat[256];
__device__ float g_lossp[128];
__device__ __align__(16) __half g_wpack[36864];  // packed fp16 conv1 weights

// ---------------- helpers ----------------
__device__ __forceinline__ float wred(float v) {
#pragma unroll
    for (int o = 16; o > 0; o >>= 1) v += __shfl_xor_sync(0xffffffffu, v, o);
    return v;
}
__device__ __forceinline__ float bsum256(float v, float* red) {
    int t = threadIdx.x; red[t] = v; __syncthreads();
#pragma unroll
    for (int s = 128; s > 0; s >>= 1) { if (t < s) red[t] += red[t + s]; __syncthreads(); }
    float r = red[0]; __syncthreads(); return r;
}
__device__ __forceinline__ float bmax256(float v, float* red) {
    int t = threadIdx.x; red[t] = v; __syncthreads();
#pragma unroll
    for (int s = 128; s > 0; s >>= 1) { if (t < s) red[t] = fmaxf(red[t], red[t + s]); __syncthreads(); }
    float r = red[0]; __syncthreads(); return r;
}

// ---------------- 0: pack conv1 weights to fp16, mma-ready layout ----------------
// layout: [chunk 4][tap 9][co 64][slot 16];  slot s -> cin = 2p + (pos&1) + 8*(pos>>1)
__global__ void k_wprep(const float* __restrict__ c1w) {
    int idx = blockIdx.x * 256 + threadIdx.x;   // 0..36863
    int slot = idx & 15;
    int co = (idx >> 4) & 63;
    int rest = idx >> 10;                        // chunk*9 + tap
    int tap = rest % 9, chunk = rest / 9;
    int p = slot >> 2, pos = slot & 3;
    int cin = 2 * p + (pos & 1) + ((pos >> 1) << 3);
    float wv = c1w[(size_t)(co * 64 + chunk * 16 + cin) * 9 + tap];
    g_wpack[idx] = __float2half_rn(wv);
}

// ---------------- 1: per-(b,c) sums of sr / tg / tg^2 ----------------
__global__ void k_colsum(const float* __restrict__ sr, const float* __restrict__ tg) {
    int bc = blockIdx.x;
    const float* ps = sr + (size_t)bc * HWC;
    const float* pt = tg + (size_t)bc * HWC;
    float s0 = 0.f, s1 = 0.f, s2 = 0.f;
    for (int i = threadIdx.x; i < HWC; i += 256) {
        s0 += ps[i];
        float t = pt[i]; s1 += t; s2 += t * t;
    }
    __shared__ float red[256];
    s0 = bsum256(s0, red); s1 = bsum256(s1, red); s2 = bsum256(s2, red);
    if (threadIdx.x == 0) { g_tsum[bc] = s0; g_T1[bc] = s1; g_T2[bc] = s2; }
}

// ---------------- 2: op0 = W * colsum(sr) + w_b * HW ----------------
__global__ void k_op0(const float* __restrict__ ww, const float* __restrict__ wb) {
    int bn = blockIdx.x; int b = bn >> 4, n = bn & 15; int cp = threadIdx.x;
    __shared__ float ts[64];
    ts[cp] = g_tsum[b * 64 + cp];
    __syncthreads();
    const float* wr = ww + (size_t)(n * 64 + cp) * 64;
    float a = 0.f;
#pragma unroll 8
    for (int c = 0; c < 64; c++) a = fmaf(wr[c], ts[c], a);
    g_op[bn * 64 + cp] = a + wb[n * 64 + cp] * (float)HWC;
}

// ---------------- 3a: opn, u = W^T opn; zero g_v ----------------
__global__ void k_u(const float* __restrict__ ww) {
    int bn = blockIdx.x; int n = bn & 15; int c = threadIdx.x;
    __shared__ float opn[64]; __shared__ float red[64];
    float o = g_op[bn * 64 + c];
    red[c] = o * o; __syncthreads();
#pragma unroll
    for (int s = 32; s > 0; s >>= 1) { if (c < s) red[c] += red[c + s]; __syncthreads(); }
    float nrm = fmaxf(sqrtf(red[0]), 1e-12f);
    opn[c] = o / nrm;
    __syncthreads();
    float u = 0.f;
    for (int cp = 0; cp < 64; cp++) u = fmaf(ww[(size_t)(n * 64 + cp) * 64 + c], opn[cp], u);
    g_u[bn * 64 + c] = u;
    g_v[bn * 64 + c] = 0.f;
}

// ---------------- 3b: logits[b,n,hw] = sum_c u[b,n,c]*sr[b,c,hw] ----------------
__global__ void k_logits(const float* __restrict__ sr) {
    int b = blockIdx.y;
    int hw = blockIdx.x * 256 + threadIdx.x;
    __shared__ float us[1024];
    for (int i = threadIdx.x; i < 1024; i += 256) us[i] = g_u[b * 1024 + i];
    __syncthreads();
    float acc[16];
#pragma unroll
    for (int n = 0; n < 16; n++) acc[n] = 0.f;
    const float* sp = sr + (size_t)b * 64 * HWC + hw;
    for (int c = 0; c < 64; c++) {
        float v = sp[(size_t)c * HWC];
#pragma unroll
        for (int n = 0; n < 16; n++) acc[n] = fmaf(us[n * 64 + c], v, acc[n]);
    }
#pragma unroll
    for (int n = 0; n < 16; n++) g_logits[(size_t)(b * 16 + n) * HWC + hw] = acc[n];
}

// ---------------- 3c: softmax over hw (optionally also to d_out cof) ----------------
__global__ void k_softmax(float* extra) {
    int bn = blockIdx.x;
    const float* l = g_logits + (size_t)bn * HWC;
    __shared__ float red[256];
    float mx = -1e30f;
    for (int i = threadIdx.x; i < HWC; i += 256) mx = fmaxf(mx, l[i]);
    mx = bmax256(mx, red);
    float se = 0.f;
    for (int i = threadIdx.x; i < HWC; i += 256) se += expf(l[i] - mx);
    se = bsum256(se, red);
    float inv = 1.f / se;
    float* cf = g_cof + (size_t)bn * HWC;
    float* ex = extra ? extra + (size_t)bn * HWC : nullptr;
    for (int i = threadIdx.x; i < HWC; i += 256) {
        float c = expf(l[i] - mx) * inv;
        cf[i] = c;
        if (ex) ex[i] = c;
    }
}

// ---------------- 3d: v[b,n,c] = sum_hw sr[b,c,hw]*cof[b,n,hw] ----------------
__global__ void k_v(const float* __restrict__ sr) {
    int ch = blockIdx.x;   // 16 chunks of 576 pixels
    int b  = blockIdx.y;
    int hw0 = ch * 576;
    __shared__ float cof_s[16 * 576];
    for (int idx = threadIdx.x; idx < 9216; idx += 256) {
        int n = idx / 576, k = idx - n * 576;
        cof_s[n * 576 + k] = g_cof[(size_t)(b * 16 + n) * HWC + hw0 + k];
    }
    __syncthreads();
    int w = threadIdx.x >> 5, lane = threadIdx.x & 31;
    for (int c = w; c < 64; c += 8) {
        const float* sp = sr + (size_t)(b * 64 + c) * HWC + hw0;
        float a[16];
#pragma unroll
        for (int n = 0; n < 16; n++) a[n] = 0.f;
        for (int k = lane; k < 576; k += 32) {
            float s = sp[k];
#pragma unroll
            for (int n = 0; n < 16; n++) a[n] = fmaf(s, cof_s[n * 576 + k], a[n]);
        }
#pragma unroll
        for (int n = 0; n < 16; n++) {
            float r = wred(a[n]);
            if (lane == 0) atomicAdd(&g_v[(b * 16 + n) * 64 + c], r);
        }
    }
}

// ---------------- 3e: op = W v + w_b ----------------
__global__ void k_op(const float* __restrict__ ww, const float* __restrict__ wb) {
    int bn = blockIdx.x; int n = bn & 15; int cp = threadIdx.x;
    __shared__ float vs[64];
    vs[cp] = g_v[bn * 64 + cp];
    __syncthreads();
    const float* wr = ww + (size_t)(n * 64 + cp) * 64;
    float a = 0.f;
#pragma unroll 8
    for (int c = 0; c < 64; c++) a = fmaf(wr[c], vs[c], a);
    g_op[bn * 64 + cp] = a + wb[n * 64 + cp];
}

// ---------------- 4: analytic GN1 affine; zero GN2 accumulators ----------------
__global__ void k_gn1AD(const float* __restrict__ g1g, const float* __restrict__ g1b) {
    int bn = blockIdx.x; int b = bn >> 4; int c = threadIdx.x;
    float op = g_op[bn * 64 + c];
    float t1 = g_T1[b * 64 + c], t2 = g_T2[b * 64 + c];
    float s1 = t1 + 9216.f * op;
    float s2 = t2 + 2.f * op * t1 + 9216.f * op * op;
    s1 += __shfl_xor_sync(0xffffffffu, s1, 1); s1 += __shfl_xor_sync(0xffffffffu, s1, 2);
    s2 += __shfl_xor_sync(0xffffffffu, s2, 1); s2 += __shfl_xor_sync(0xffffffffu, s2, 2);
    float mu  = s1 * (1.f / 36864.f);
    float var = s2 * (1.f / 36864.f) - mu * mu;
    float inv = rsqrtf(var + EPSN);
    g_A1[bn * 64 + c] = g1g[c] * inv;
    g_D1[bn * 64 + c] = (op - mu) * inv * g1g[c] + g1b[c];
    g_gn2s[bn * 64 + c] = 0.f; g_gn2q[bn * 64 + c] = 0.f;
}

// ---------------- 5: fused GN1+ReLU+conv3x3(64->64) via mma.m16n8k16 fp16 --------
// Same mainloop as R4; fills replaced: weights from g_wpack via uint4 copy,
// input via shift-only indexing + half2 stores (conflict-free).
__global__ void __launch_bounds__(256, 2) k_conv1(const float* __restrict__ tg,
                                                  const float* __restrict__ c1b) {
    int bn = blockIdx.z, b = bn >> 4;
    int gx0 = blockIdx.x * 16, gy0 = blockIdx.y * 16;
    int tid = threadIdx.x;
    int warp = tid >> 5, lane = tid & 31;
    int gid = lane >> 2, tg4 = lane & 3;
    int mgroup = warp & 1, ngroup = warp >> 1;

    __shared__ __half in_s[324 * 16];     // 10368 B
    __shared__ __half w_s[9 * 64 * 16];   // 18432 B
    __shared__ float As[64], Ds[64], Bs[64];

    if (tid < 64) { As[tid] = g_A1[bn * 64 + tid]; Ds[tid] = g_D1[bn * 64 + tid]; Bs[tid] = c1b[tid]; }

    float acc[2][8][4];
#pragma unroll
    for (int s = 0; s < 2; s++)
#pragma unroll
        for (int t = 0; t < 8; t++) { acc[s][t][0] = 0.f; acc[s][t][1] = 0.f; acc[s][t][2] = 0.f; acc[s][t][3] = 0.f; }

    int sidx[8];
#pragma unroll
    for (int t = 0; t < 8; t++) {
        int n = ngroup * 64 + t * 8 + gid;
        sidx[t] = (n >> 4) * 18 + (n & 15);
    }

    const float* tgb = tg + (size_t)b * 64 * HWC;
    const uint4* wp4 = (const uint4*)g_wpack;

    for (int cc4 = 0; cc4 < 4; cc4++) {
        int cc = cc4 * 16;
        __syncthreads();
        // weights: straight uint4 copy of pre-packed fp16 (1152 uint4)
        {
            uint4* ws4 = (uint4*)w_s;
            const uint4* src = wp4 + cc4 * 1152;
#pragma unroll
            for (int i = 0; i < 4; i++) {
                int idx = tid + i * 256;
                ws4[idx] = src[idx];
            }
            int idx = tid + 1024;
            if (idx < 1152) ws4[idx] = src[idx];
        }
        // input halo tile: GN1 affine + ReLU -> half2 stores, shift-only indexing
        // idx -> sp = idx>>3, j = idx&7; slot pair (2j,2j+1) holds cins:
        //   j even: {j, j+1};  j odd: {j+7, j+8}
        for (int idx = tid; idx < 2592; idx += 256) {
            int sp = idx >> 3, j = idx & 7;
            int cin0 = (j & 1) ? (j + 7) : j;
            int rr = sp / 18, c2 = sp - rr * 18;
            int gy = gy0 + rr - 1, gx = gx0 + c2 - 1;
            float v0 = 0.f, v1 = 0.f;
            if ((unsigned)gy < 96u && (unsigned)gx < 96u) {
                int ch0 = cc + cin0;
                size_t base = (size_t)gy * 96 + gx;
                float t0 = tgb[(size_t)ch0 * HWC + base];
                float t1 = tgb[(size_t)(ch0 + 1) * HWC + base];
                v0 = fmaxf(fmaf(t0, As[ch0], Ds[ch0]), 0.f);
                v1 = fmaxf(fmaf(t1, As[ch0 + 1], Ds[ch0 + 1]), 0.f);
            }
            ((__half2*)in_s)[sp * 8 + j] = __floats2half2_rn(v0, v1);
        }
        __syncthreads();
#pragma unroll
        for (int ks = 0; ks < 9; ks++) {
            int toff = (ks / 3) * 18 + (ks % 3);
            uint2 afr[2][2];
#pragma unroll
            for (int s = 0; s < 2; s++) {
                int co_r0 = mgroup * 32 + s * 16 + gid;
                afr[s][0] = *(const uint2*)(w_s + (ks * 64 + co_r0) * 16 + tg4 * 4);
                afr[s][1] = *(const uint2*)(w_s + (ks * 64 + co_r0 + 8) * 16 + tg4 * 4);
            }
#pragma unroll
            for (int t = 0; t < 8; t++) {
                uint2 bb = *(const uint2*)(in_s + (toff + sidx[t]) * 16 + tg4 * 4);
#pragma unroll
                for (int s = 0; s < 2; s++) {
                    asm volatile("mma.sync.aligned.m16n8k16.row.col.f32.f16.f16.f32 "
                                 "{%0,%1,%2,%3}, {%4,%5,%6,%7}, {%8,%9}, {%0,%1,%2,%3};"
                                 : "+f"(acc[s][t][0]), "+f"(acc[s][t][1]),
                                   "+f"(acc[s][t][2]), "+f"(acc[s][t][3])
                                 : "r"(afr[s][0].x), "r"(afr[s][1].x),
                                   "r"(afr[s][0].y), "r"(afr[s][1].y),
                                   "r"(bb.x), "r"(bb.y));
                }
            }
        }
    }

    // epilogue: bias, store y1, GN2 stats
#pragma unroll
    for (int s = 0; s < 2; s++) {
        int co0 = mgroup * 32 + s * 16 + gid;
        int co1 = co0 + 8;
        float b0v = Bs[co0], b1v = Bs[co1];
        float s0 = 0.f, q0 = 0.f, s1 = 0.f, q1 = 0.f;
        float* yb0 = g_y1 + (size_t)(bn * 64 + co0) * HWC;
        float* yb1 = g_y1 + (size_t)(bn * 64 + co1) * HWC;
#pragma unroll
        for (int t = 0; t < 8; t++) {
            int n = ngroup * 64 + t * 8 + tg4 * 2;
            int r = n >> 4, c = n & 15;
            size_t po = (size_t)(gy0 + r) * 96 + gx0 + c;
            float v00 = acc[s][t][0] + b0v, v01 = acc[s][t][1] + b0v;
            float v10 = acc[s][t][2] + b1v, v11 = acc[s][t][3] + b1v;
            yb0[po] = v00; yb0[po + 1] = v01;
            yb1[po] = v10; yb1[po + 1] = v11;
            s0 += v00 + v01; q0 += v00 * v00 + v01 * v01;
            s1 += v10 + v11; q1 += v10 * v10 + v11 * v11;
        }
        s0 += __shfl_xor_sync(0xffffffffu, s0, 1); s0 += __shfl_xor_sync(0xffffffffu, s0, 2);
        q0 += __shfl_xor_sync(0xffffffffu, q0, 1); q0 += __shfl_xor_sync(0xffffffffu, q0, 2);
        s1 += __shfl_xor_sync(0xffffffffu, s1, 1); s1 += __shfl_xor_sync(0xffffffffu, s1, 2);
        q1 += __shfl_xor_sync(0xffffffffu, q1, 1); q1 += __shfl_xor_sync(0xffffffffu, q1, 2);
        if (tg4 == 0) {
            atomicAdd(&g_gn2s[bn * 64 + co0], s0); atomicAdd(&g_gn2q[bn * 64 + co0], q0);
            atomicAdd(&g_gn2s[bn * 64 + co1], s1); atomicAdd(&g_gn2q[bn * 64 + co1], q1);
        }
    }
}

// ---------------- 6: GN2 affine params (reuse g_A1/g_D1) ----------------
__global__ void k_gn2fin(const float* __restrict__ g2g, const float* __restrict__ g2b) {
    int bn = blockIdx.x, c = threadIdx.x;
    float s = g_gn2s[bn * 64 + c], q = g_gn2q[bn * 64 + c];
    s += __shfl_xor_sync(0xffffffffu, s, 1); s += __shfl_xor_sync(0xffffffffu, s, 2);
    q += __shfl_xor_sync(0xffffffffu, q, 1); q += __shfl_xor_sync(0xffffffffu, q, 2);
    float mu = s * (1.f / 36864.f), var = q * (1.f / 36864.f) - mu * mu;
    float inv = rsqrtf(var + EPSN);
    g_A1[bn * 64 + c] = g2g[c] * inv;
    g_D1[bn * 64 + c] = g2b[c] - mu * inv * g2g[c];
}

// ---------------- 7: fused GN2+ReLU+conv3x3(64->1) -> msk (8-ch chunks) --------
__global__ void __launch_bounds__(256) k_conv2(const float* __restrict__ c2w,
                                               const float* __restrict__ c2b,
                                               float* __restrict__ msk) {
    int bn = blockIdx.z; int gy0 = blockIdx.y * 16, gx0 = blockIdx.x * 16;
    int t = threadIdx.x, ty = t >> 4, tx = t & 15;
    __shared__ float tile[8 * 324];   // 8ch x 18x18
    __shared__ float w2[576];
    __shared__ float A[64], D[64];
    for (int i = t; i < 576; i += 256) w2[i] = c2w[i];
    if (t < 64) { A[t] = g_A1[bn * 64 + t]; D[t] = g_D1[bn * 64 + t]; }
    float acc = c2b[0];
    const float* y = g_y1 + (size_t)bn * 64 * HWC;
    for (int cc = 0; cc < 64; cc += 8) {
        __syncthreads();
        for (int idx = t; idx < 2592; idx += 256) {
            int ch = idx / 324, rem = idx - ch * 324, r = rem / 18, c = rem - r * 18;
            int gy = gy0 + r - 1, gx = gx0 + c - 1;
            float v = 0.f;
            if ((unsigned)gy < 96u && (unsigned)gx < 96u)
                v = fmaxf(fmaf(y[(size_t)(cc + ch) * HWC + gy * 96 + gx], A[cc + ch], D[cc + ch]), 0.f);
            tile[idx] = v;
        }
        __syncthreads();
#pragma unroll
        for (int ch = 0; ch < 8; ch++)
#pragma unroll
            for (int kr = 0; kr < 3; kr++)
#pragma unroll
                for (int kc = 0; kc < 3; kc++)
                    acc = fmaf(w2[(cc + ch) * 9 + kr * 3 + kc],
                               tile[ch * 324 + (ty + kr) * 18 + tx + kc], acc);
    }
    msk[(size_t)bn * HWC + (gy0 + ty) * 96 + gx0 + tx] = acc;
}

// ---------------- 8: per-bn softmax of msk, center loss, IN1 stats ----------------
__global__ void k_msk_stats(const float* __restrict__ msk) {
    int bn = blockIdx.x; int t = threadIdx.x;
    const float* m = msk + (size_t)bn * HWC;
    __shared__ float red[256];
    float mx = -1e30f;
    for (int i = t; i < HWC; i += 256) mx = fmaxf(mx, m[i]);
    mx = bmax256(mx, red);
    float se = 0.f, s1 = 0.f, s2 = 0.f;
    for (int i = t; i < HWC; i += 256) { float v = m[i]; se += expf(v - mx); s1 += v; s2 += v * v; }
    se = bsum256(se, red); s1 = bsum256(s1, red); s2 = bsum256(s2, red);
    float inv_se = 1.f / se;
    float ey = 0.f, ex = 0.f, ey2 = 0.f, ex2 = 0.f;
    const float st = 2.f / 95.f;
    for (int i = t; i < HWC; i += 256) {
        float c = expf(m[i] - mx) * inv_se;
        int ii = i / 96, jj = i - ii * 96;
        float yv = -1.f + st * ii, xv = -1.f + st * jj;
        ey += c * yv; ex += c * xv; ey2 += c * yv * yv; ex2 += c * xv * xv;
    }
    ey = bsum256(ey, red); ex = bsum256(ex, red);
    ey2 = bsum256(ey2, red); ex2 = bsum256(ex2, red);
    if (t == 0) {
        g_lossp[bn] = ey2 - ey * ey + ex2 - ex * ex;
        float mu = s1 / 9216.f; float var = s2 / 9216.f - mu * mu;
        g_mstat[2 * bn] = mu; g_mstat[2 * bn + 1] = rsqrtf(var + EPSN);
        g_in2s[bn] = 0.f; g_in2q[bn] = 0.f;
    }
}

// ---------------- 9: centr loss reduction ----------------
__global__ void k_loss(float* out) {
    __shared__ float red[128];
    int t = threadIdx.x;
    red[t] = g_lossp[t]; __syncthreads();
#pragma unroll
    for (int s = 64; s > 0; s >>= 1) { if (t < s) red[t] += red[t + s]; __syncthreads(); }
    if (t == 0) out[0] = red[0] * (1.f / 128.f);
}

// ---------------- 10: IN1+ReLU+1x1 conv (16->16) + IN2 stat accumulation ---------
__global__ void k_gen1(const float* __restrict__ msk, const float* __restrict__ in1g,
                       const float* __restrict__ in1b, const float* __restrict__ c3w,
                       const float* __restrict__ c3b) {
    int b = blockIdx.y; int hw = blockIdx.x * 256 + threadIdx.x;
    int t = threadIdx.x;
    __shared__ float w3[256], b3[16], mus[16], invs[16], g1[16], bb1[16];
    __shared__ float bs_[16], bq_[16];
    if (t < 256) w3[t] = c3w[t];
    if (t < 16) {
        b3[t] = c3b[t]; int bn = b * 16 + t;
        mus[t] = g_mstat[2 * bn]; invs[t] = g_mstat[2 * bn + 1];
        g1[t] = in1g[t]; bb1[t] = in1b[t]; bs_[t] = 0.f; bq_[t] = 0.f;
    }
    __syncthreads();
    float r[16];
#pragma unroll
    for (int n = 0; n < 16; n++) {
        float m = msk[(size_t)(b * 16 + n) * HWC + hw];
        r[n] = fmaxf((m - mus[n]) * invs[n] * g1[n] + bb1[n], 0.f);
    }
#pragma unroll
    for (int o = 0; o < 16; o++) {
        float a = b3[o];
#pragma unroll
        for (int n = 0; n < 16; n++) a = fmaf(w3[o * 16 + n], r[n], a);
        g_g2[(size_t)(b * 16 + o) * HWC + hw] = a;
        float s = wred(a), q = wred(a * a);
        if ((t & 31) == 0) { atomicAdd(&bs_[o], s); atomicAdd(&bq_[o], q); }
    }
    __syncthreads();
    if (t < 16) { atomicAdd(&g_in2s[b * 16 + t], bs_[t]); atomicAdd(&g_in2q[b * 16 + t], bq_[t]); }
}

// ---------------- 11: IN2 stats finalize ----------------
__global__ void k_in2fin() {
    int i = threadIdx.x;
    float mu = g_in2s[i] / 9216.f;
    float var = g_in2q[i] / 9216.f - mu * mu;
    g_in2stat[2 * i] = mu; g_in2stat[2 * i + 1] = rsqrtf(var + EPSN);
}

// ---------------- 12: IN2+ReLU+1x1(16->3)+sigmoid -> rec ----------------
__global__ void k_rec(const float* __restrict__ in2g, const float* __restrict__ in2b,
                      const float* __restrict__ c4w, const float* __restrict__ c4b,
                      float* __restrict__ out) {
    int b = blockIdx.y; int hw = blockIdx.x * 256 + threadIdx.x; int t = threadIdx.x;
    __shared__ float w4[48], mus[16], invs[16], g2[16], bb2[16];
    if (t < 48) w4[t] = c4w[t];
    if (t < 16) {
        int bo = b * 16 + t;
        mus[t] = g_in2stat[2 * bo]; invs[t] = g_in2stat[2 * bo + 1];
        g2[t] = in2g[t]; bb2[t] = in2b[t];
    }
    __syncthreads();
    float x[16];
#pragma unroll
    for (int o = 0; o < 16; o++) {
        float v = g_g2[(size_t)(b * 16 + o) * HWC + hw];
        x[o] = fmaxf((v - mus[o]) * invs[o] * g2[o] + bb2[o], 0.f);
    }
#pragma unroll
    for (int o2 = 0; o2 < 3; o2++) {
        float a = c4b[o2];
#pragma unroll
        for (int o = 0; o < 16; o++) a = fmaf(w4[o2 * 16 + o], x[o], a);
        out[(size_t)(b * 3 + o2) * HWC + hw] = 1.f / (1.f + expf(-a));
    }
}

// ---------------- 13: op_out = op[bnc] * msk[bn,hw] ----------------
__global__ void k_opout(const float* __restrict__ msk, float* __restrict__ out) {
    int bn = blockIdx.y; int hw = blockIdx.x * 256 + threadIdx.x;
    __shared__ float ops[64];
    if (threadIdx.x < 64) ops[threadIdx.x] = g_op[bn * 64 + threadIdx.x];
    __syncthreads();
    float m = msk[(size_t)bn * HWC + hw];
    float* o = out + (size_t)bn * 64 * HWC + hw;
#pragma unroll 8
    for (int c = 0; c < 64; c++) o[(size_t)c * HWC] = ops[c] * m;
}

// ---------------- launch ----------------
extern "C" void kernel_launch(void* const* d_in, const int* in_sizes, int n_in,
                              void* d_out, int out_size) {
    const float* sr   = (const float*)d_in[0];
    const float* tg   = (const float*)d_in[1];
    const float* ww   = (const float*)d_in[2];
    const float* wb   = (const float*)d_in[3];
    const float* gn1g = (const float*)d_in[4];
    const float* gn1b = (const float*)d_in[5];
    const float* c1w  = (const float*)d_in[6];
    const float* c1b  = (const float*)d_in[7];
    const float* gn2g = (const float*)d_in[8];
    const float* gn2b = (const float*)d_in[9];
    const float* c2w  = (const float*)d_in[10];
    const float* c2b  = (const float*)d_in[11];
    const float* in1g = (const float*)d_in[12];
    const float* in1b = (const float*)d_in[13];
    const float* c3w  = (const float*)d_in[14];
    const float* c3b  = (const float*)d_in[15];
    const float* in2g = (const float*)d_in[16];
    const float* in2b = (const float*)d_in[17];
    const float* c4w  = (const float*)d_in[18];
    const float* c4b  = (const float*)d_in[19];
    float* out = (float*)d_out;
    float* out_msk  = out + 75497472;
    float* out_rec  = out + 76677120;
    float* out_loss = out + 76898304;
    float* out_cof  = out + 76898305;

    k_wprep<<<144, 256>>>(c1w);
    k_colsum<<<512, 256>>>(sr, tg);
    k_op0<<<128, 64>>>(ww, wb);
    for (int it = 0; it < 3; it++) {
        k_u<<<128, 64>>>(ww);
        k_logits<<<dim3(36, 8), 256>>>(sr);
        k_softmax<<<128, 256>>>(it == 2 ? out_cof : (float*)nullptr);
        k_v<<<dim3(16, 8), 256>>>(sr);
        k_op<<<128, 64>>>(ww, wb);
    }
    k_gn1AD<<<128, 64>>>(gn1g, gn1b);
    k_conv1<<<dim3(6, 6, 128), 256>>>(tg, c1b);
    k_gn2fin<<<128, 64>>>(gn2g, gn2b);
    k_conv2<<<dim3(6, 6, 128), 256>>>(c2w, c2b, out_msk);
    k_msk_stats<<<128, 256>>>(out_msk);
    k_loss<<<1, 128>>>(out_loss);
    k_gen1<<<dim3(36, 8), 256>>>(out_msk, in1g, in1b, c3w, c3b);
    k_in2fin<<<1, 128>>>();
    k_rec<<<dim3(36, 8), 256>>>(in2g, in2b, c4w, c4b, out_rec);
    k_opout<<<dim3(36, 128), 256>>>(out_msk, out);
}